// round 14
// baseline (speedup 1.0000x reference)
#include <cuda_runtime.h>
#include <cuda_fp16.h>
#include <cstdint>

#define NN 50000
#define EE 800000
#define ETOT (EE + NN)
#define GG 128
#define NEG_SLOPE 0.2f
#define RB 49   // ceil(NN/1024)

typedef unsigned long long ull;

union F4U { float4 f; ull u[2]; };
union F2U { float2 f; ull u; };

__device__ __forceinline__ ull fma2(ull a, ull b, ull c) {
    ull d; asm("fma.rn.f32x2 %0,%1,%2,%3;" : "=l"(d) : "l"(a), "l"(b), "l"(c)); return d;
}
__device__ __forceinline__ ull add2(ull a, ull b) {
    ull d; asm("add.rn.f32x2 %0,%1,%2;" : "=l"(d) : "l"(a), "l"(b)); return d;
}
__device__ __forceinline__ ull pack2(float x) {
    F2U t; t.f = make_float2(x, x); return t.u;
}
__device__ __forceinline__ float2 unpack2(ull v) { F2U t; t.u = v; return t.f; }

__device__ __forceinline__ uint32_t smem_u32(const void* p) {
    uint32_t a;
    asm("{ .reg .u64 t; cvta.to.shared.u64 t, %1; cvt.u32.u64 %0, t; }" : "=r"(a) : "l"(p));
    return a;
}
__device__ __forceinline__ void ldsm4(uint32_t& r0, uint32_t& r1, uint32_t& r2, uint32_t& r3,
                                      uint32_t addr) {
    asm volatile("ldmatrix.sync.aligned.m8n8.x4.shared.b16 {%0,%1,%2,%3}, [%4];"
                 : "=r"(r0), "=r"(r1), "=r"(r2), "=r"(r3) : "r"(addr));
}
__device__ __forceinline__ void mma16816(float* c, uint32_t a0, uint32_t a1, uint32_t a2,
                                         uint32_t a3, uint32_t b0, uint32_t b1) {
    asm volatile(
        "mma.sync.aligned.m16n8k16.row.col.f32.f16.f16.f32 "
        "{%0,%1,%2,%3},{%4,%5,%6,%7},{%8,%9},{%0,%1,%2,%3};"
        : "+f"(c[0]), "+f"(c[1]), "+f"(c[2]), "+f"(c[3])
        : "r"(a0), "r"(a1), "r"(a2), "r"(a3), "r"(b0), "r"(b1));
}

// ---------------- scratch ----------------
__device__ float g_x1[NN * 16];
__device__ float g_x2[NN * 32];
__device__ float g_h [NN * 16];
__device__ float g_h2[NN * 32];
__device__ __half g_hb[NN * 256];
__device__ __half g_x2b[NN * 32];
__device__ __half g_x3b[NN * 128];
__device__ __half g_x4b[NN * 256];
__device__ __half g_w3t[128 * 32];
__device__ __half g_w4t[256 * 128];
__device__ float g_asrc[NN * 8];
__device__ float g_adst[NN * 8];
__device__ float g_dinv[NN];
__device__ int   g_counts[NN];
__device__ int   g_rank[ETOT];
__device__ int   g_bsum[RB];
__device__ int   g_rowptr[NN + 1];
__device__ int   g_csr_src[ETOT];
__device__ int   g_gstart[GG + 1];
__device__ float g_pool[GG * 432];

// ---------------- CSR build ----------------
// count + per-edge rank, 4 edges per thread for MLP. EE and ETOT are 4-divisible,
// so each 4-pack is entirely real-edge or entirely self-loop.
__global__ void count_edges_kernel(const int* __restrict__ ei, int* __restrict__ counts,
                                   int* __restrict__ rank) {
    int e4 = (blockIdx.x * blockDim.x + threadIdx.x) * 4;
    if (e4 >= ETOT) return;
    int4 r;
    if (e4 < EE) {
        int4 d = *(const int4*)&ei[EE + e4];
        r.x = atomicAdd(&counts[d.x], 1);
        r.y = atomicAdd(&counts[d.y], 1);
        r.z = atomicAdd(&counts[d.z], 1);
        r.w = atomicAdd(&counts[d.w], 1);
    } else {
        int n0 = e4 - EE;
        r.x = atomicAdd(&counts[n0 + 0], 1);
        r.y = atomicAdd(&counts[n0 + 1], 1);
        r.z = atomicAdd(&counts[n0 + 2], 1);
        r.w = atomicAdd(&counts[n0 + 3], 1);
    }
    *(int4*)&rank[e4] = r;
}

__global__ void scan_reduce_kernel(const int* __restrict__ counts, int* __restrict__ bsum) {
    __shared__ int ws[32];
    int i = blockIdx.x * 1024 + threadIdx.x;
    int v = (i < NN) ? counts[i] : 0;
    int lane = threadIdx.x & 31, w = threadIdx.x >> 5;
#pragma unroll
    for (int o = 16; o; o >>= 1) v += __shfl_xor_sync(0xffffffffu, v, o);
    if (lane == 0) ws[w] = v;
    __syncthreads();
    if (w == 0) {
        int s = ws[lane];
#pragma unroll
        for (int o = 16; o; o >>= 1) s += __shfl_xor_sync(0xffffffffu, s, o);
        if (lane == 0) bsum[blockIdx.x] = s;
    }
}

// scan_apply with inline cross-block offset
__global__ void scan_apply_kernel(const int* __restrict__ counts, const int* __restrict__ bsum,
                                  int* __restrict__ rowptr, float* __restrict__ dinv) {
    __shared__ int ws[32];
    __shared__ int boff_sh;
    int i = blockIdx.x * 1024 + threadIdx.x;
    int cnt = (i < NN) ? counts[i] : 0;
    int lane = threadIdx.x & 31, w = threadIdx.x >> 5;
    int v = cnt;
#pragma unroll
    for (int o = 1; o < 32; o <<= 1) {
        int u = __shfl_up_sync(0xffffffffu, v, o);
        if (lane >= o) v += u;
    }
    if (lane == 31) ws[w] = v;
    __syncthreads();
    if (w == 0) {
        int s = ws[lane];
#pragma unroll
        for (int o = 1; o < 32; o <<= 1) {
            int u = __shfl_up_sync(0xffffffffu, s, o);
            if (lane >= o) s += u;
        }
        ws[lane] = s;
    }
    if (w == 1) {
        int lim = (int)blockIdx.x < RB ? (int)blockIdx.x : RB;
        int v2 = (lane < lim) ? bsum[lane] : 0;
        if (lane + 32 < lim) v2 += bsum[lane + 32];
#pragma unroll
        for (int o = 16; o; o >>= 1) v2 += __shfl_xor_sync(0xffffffffu, v2, o);
        if (lane == 0) boff_sh = v2;
    }
    __syncthreads();
    int incl = v + (w ? ws[w - 1] : 0) + boff_sh;
    if (i < NN) {
        rowptr[i + 1] = incl;
        dinv[i] = rsqrtf((float)(cnt > 0 ? cnt : 1));
    }
    if (i == 0) rowptr[0] = 0;
}

// atomic-free fill, 4 edges per thread
__global__ void fill_csr_kernel(const int* __restrict__ ei, const int* __restrict__ rowptr,
                                const int* __restrict__ rank, int* __restrict__ csr) {
    int e4 = (blockIdx.x * blockDim.x + threadIdx.x) * 4;
    if (e4 >= ETOT) return;
    int4 r = *(const int4*)&rank[e4];
    if (e4 < EE) {
        int4 s = *(const int4*)&ei[e4];
        int4 d = *(const int4*)&ei[EE + e4];
        int p0 = rowptr[d.x], p1 = rowptr[d.y], p2 = rowptr[d.z], p3 = rowptr[d.w];
        csr[p0 + r.x] = s.x;
        csr[p1 + r.y] = s.y;
        csr[p2 + r.z] = s.z;
        csr[p3 + r.w] = s.w;
    } else {
        int n0 = e4 - EE;
        int p0 = rowptr[n0], p1 = rowptr[n0 + 1], p2 = rowptr[n0 + 2], p3 = rowptr[n0 + 3];
        csr[p0 + r.x] = n0;
        csr[p1 + r.y] = n0 + 1;
        csr[p2 + r.z] = n0 + 2;
        csr[p3 + r.w] = n0 + 3;
    }
}

__global__ void gstart_kernel(const int* __restrict__ batch, int* __restrict__ gstart) {
    int n = blockIdx.x * blockDim.x + threadIdx.x;
    if (n >= NN) return;
    int b = batch[n];
    if (n == 0) { for (int g = 0; g <= b; g++) gstart[g] = 0; }
    else {
        int pb = batch[n - 1];
        for (int g = pb + 1; g <= b; g++) gstart[g] = n;
    }
    if (n == NN - 1) { for (int g = b + 1; g <= GG; g++) gstart[g] = NN; }
}

// ---- W transpose to fp16 [NOUT][KEL] ----
template<int KEL, int NOUT>
__global__ void wt_kernel(const float* __restrict__ W, __half* __restrict__ Wt) {
    int idx = blockIdx.x * 256 + threadIdx.x;
    if (idx >= KEL * NOUT) return;
    int n = idx / KEL, k = idx % KEL;
    Wt[idx] = __float2half(W[k * NOUT + n]);
}

// ---------------- small GEMM (fp32) ----------------
template<int K, int M>
__global__ void gemm_small_kernel(const float* __restrict__ X, const float* __restrict__ W,
                                  float* __restrict__ Y) {
    constexpr int CT = M;
    constexpr int KC = (K < 64) ? K : 64;
    constexpr int TX = CT / 4;
    constexpr int NT = TX * 16;
    constexpr int RP = 68;
    __shared__ float Xs[KC * RP];
    __shared__ float Ws[KC * CT];
    int row0 = blockIdx.x * 64;
    int tid = threadIdx.y * TX + threadIdx.x;
    float acc[4][4] = {};
    for (int k0 = 0; k0 < K; k0 += KC) {
        for (int idx = tid; idx < 64 * KC; idx += NT) {
            int r = idx / KC, k = idx % KC;
            int gr = row0 + r;
            Xs[k * RP + r] = (gr < NN) ? X[gr * K + k0 + k] : 0.f;
        }
        for (int idx = tid; idx < KC * CT; idx += NT) {
            int k = idx / CT, c = idx % CT;
            Ws[k * CT + c] = W[(k0 + k) * M + c];
        }
        __syncthreads();
#pragma unroll 8
        for (int k = 0; k < KC; k++) {
            float4 xv = *(const float4*)&Xs[k * RP + 4 * threadIdx.y];
            float4 wv = *(const float4*)&Ws[k * CT + 4 * threadIdx.x];
            float xa[4] = {xv.x, xv.y, xv.z, xv.w};
            float wa[4] = {wv.x, wv.y, wv.z, wv.w};
#pragma unroll
            for (int i = 0; i < 4; i++)
#pragma unroll
                for (int j = 0; j < 4; j++)
                    acc[i][j] += xa[i] * wa[j];
        }
        __syncthreads();
    }
#pragma unroll
    for (int i = 0; i < 4; i++) {
        int r = row0 + 4 * threadIdx.y + i;
        if (r < NN) {
            float4 o = make_float4(acc[i][0], acc[i][1], acc[i][2], acc[i][3]);
            *(float4*)&Y[r * M + 4 * threadIdx.x] = o;
        }
    }
}

// ---------------- HMMA GEMM: h = X@W (fp16 in/out), fused attention coefficients ----------------
template<int KEL, int NOUT>
__global__ __launch_bounds__(256) void gemm_mma_kernel(
        const __half* __restrict__ Xb, const __half* __restrict__ Wt,
        const float* __restrict__ att_s, const float* __restrict__ att_d,
        __half* __restrict__ Yb, float* __restrict__ asrc, float* __restrict__ adst) {
    constexpr int H = NOUT / 32;
    constexpr int KP = KEL + 8;
    constexpr int KPB = KP * 2;
    constexpr int A_OFF = 0;
    constexpr int B_OFF = 64 * KPB;
    constexpr int ATT_OFF = B_OFF + NOUT * KPB;
    constexpr int AU = KEL / 8;
    constexpr int NTILES = NOUT / 16;

    extern __shared__ char smem[];
    uint32_t sb = smem_u32(smem);
    int tid = threadIdx.x, w = tid >> 5, lane = tid & 31;
    int row0 = blockIdx.x * 64;

    for (int idx = tid; idx < 64 * AU; idx += 256) {
        int r = idx / AU, u = idx % AU;
        int gr = row0 + r;
        uint4 v = make_uint4(0, 0, 0, 0);
        if (gr < NN) v = *(const uint4*)&Xb[(size_t)gr * KEL + u * 8];
        *(uint4*)(smem + A_OFF + r * KPB + u * 16) = v;
    }
    for (int idx = tid; idx < NOUT * AU; idx += 256) {
        int r = idx / AU, u = idx % AU;
        *(uint4*)(smem + B_OFF + r * KPB + u * 16) = *(const uint4*)&Wt[r * KEL + u * 8];
    }
    float* att_sh = (float*)(smem + ATT_OFF);
    for (int idx = tid; idx < 2 * H * 32; idx += 256)
        att_sh[idx] = (idx < H * 32) ? att_s[idx] : att_d[idx - H * 32];
    __syncthreads();

    int wr = w >> 1, wc = w & 1;
    float acc[NTILES][4];
#pragma unroll
    for (int t = 0; t < NTILES; t++)
#pragma unroll
        for (int q = 0; q < 4; q++) acc[t][q] = 0.f;

    uint32_t aaddr = sb + A_OFF + (wr * 16 + (lane & 15)) * KPB + ((lane >> 4) << 4);
    uint32_t baddr = sb + B_OFF +
                     (wc * (NOUT / 2) + (lane & 7) + ((lane >> 4) << 3)) * KPB +
                     (((lane >> 3) & 1) << 4);
#pragma unroll
    for (int ks = 0; ks < KEL / 16; ks++) {
        uint32_t a0, a1, a2, a3;
        ldsm4(a0, a1, a2, a3, aaddr + ks * 32);
#pragma unroll
        for (int p = 0; p < NTILES / 2; p++) {
            uint32_t b0, b1, b2, b3;
            ldsm4(b0, b1, b2, b3, baddr + p * 16 * KPB + ks * 32);
            mma16816(acc[2 * p],     a0, a1, a2, a3, b0, b1);
            mma16816(acc[2 * p + 1], a0, a1, a2, a3, b2, b3);
        }
    }

    int g = lane >> 2;
    int r0g = row0 + wr * 16 + g;
    int r1g = r0g + 8;
    constexpr int HLOC = H / 2;
#pragma unroll
    for (int hh = 0; hh < HLOC; hh++) {
        int ghead = wc * HLOC + hh;
        float s0 = 0.f, d0 = 0.f, s1 = 0.f, d1 = 0.f;
#pragma unroll
        for (int t4 = 0; t4 < 4; t4++) {
            int t = hh * 4 + t4;
            int cih = t4 * 8 + (lane & 3) * 2;
            float aS0 = att_sh[ghead * 32 + cih];
            float aS1 = att_sh[ghead * 32 + cih + 1];
            float aD0 = att_sh[H * 32 + ghead * 32 + cih];
            float aD1 = att_sh[H * 32 + ghead * 32 + cih + 1];
            s0 += acc[t][0] * aS0 + acc[t][1] * aS1;
            d0 += acc[t][0] * aD0 + acc[t][1] * aD1;
            s1 += acc[t][2] * aS0 + acc[t][3] * aS1;
            d1 += acc[t][2] * aD0 + acc[t][3] * aD1;
        }
#pragma unroll
        for (int o = 1; o <= 2; o <<= 1) {
            s0 += __shfl_xor_sync(0xffffffffu, s0, o);
            d0 += __shfl_xor_sync(0xffffffffu, d0, o);
            s1 += __shfl_xor_sync(0xffffffffu, s1, o);
            d1 += __shfl_xor_sync(0xffffffffu, d1, o);
        }
        if ((lane & 3) == 0) {
            if (r0g < NN) { asrc[r0g * H + ghead] = s0; adst[r0g * H + ghead] = d0; }
            if (r1g < NN) { asrc[r1g * H + ghead] = s1; adst[r1g * H + ghead] = d1; }
        }
    }
#pragma unroll
    for (int t = 0; t < NTILES; t++) {
        int col = wc * (NOUT / 2) + t * 8 + (lane & 3) * 2;
        if (r0g < NN) {
            __half2 h2 = __floats2half2_rn(acc[t][0], acc[t][1]);
            *(uint32_t*)&Yb[(size_t)r0g * NOUT + col] = *(uint32_t*)&h2;
        }
        if (r1g < NN) {
            __half2 h2 = __floats2half2_rn(acc[t][2], acc[t][3]);
            *(uint32_t*)&Yb[(size_t)r1g * NOUT + col] = *(uint32_t*)&h2;
        }
    }
}

// ---------------- GCN layer-1 aggregate + fused x1@W2 GEMM ----------------
__global__ __launch_bounds__(256) void gcn1_fused_kernel(
        const float* __restrict__ h, const float* __restrict__ dinv,
        const int* __restrict__ rowptr, const int* __restrict__ csr,
        const float* __restrict__ bias, const float* __restrict__ W2,
        float* __restrict__ x1out, float* __restrict__ h2out) {
    __shared__ float W2s[512];
    int tid = threadIdx.x;
    for (int idx = tid; idx < 512; idx += 256) W2s[idx] = W2[idx];
    __syncthreads();

    int gtid = blockIdx.x * 256 + tid;
    int n = gtid >> 2;
    int tg = tid & 3;
    int lane = tid & 31;
    bool valid = n < NN;
    int ch = 4 * tg;
    int r0 = 0, r1 = 0;
    if (valid) { r0 = rowptr[n]; r1 = rowptr[n + 1]; }
    const float* hb = h + ch;
    ull a0 = 0ull, a1 = 0ull;
    for (int j = r0; j < r1; j++) {
        int s = csr[j];
        ull dv2 = pack2(dinv[s]);
        F4U hv; hv.f = *(const float4*)(hb + s * 16);
        a0 = fma2(hv.u[0], dv2, a0);
        a1 = fma2(hv.u[1], dv2, a1);
    }
    float dn = valid ? dinv[n] : 0.f;
    float2 r01 = unpack2(a0), r23 = unpack2(a1);
    float4 b = *(const float4*)&bias[ch];
    float4 o;
    o.x = fmaxf(r01.x * dn + b.x, 0.f);
    o.y = fmaxf(r01.y * dn + b.y, 0.f);
    o.z = fmaxf(r23.x * dn + b.z, 0.f);
    o.w = fmaxf(r23.y * dn + b.w, 0.f);
    if (valid) *(float4*)&x1out[n * 16 + ch] = o;

    float xv[16];
    int baseq = lane & ~3;
#pragma unroll
    for (int q = 0; q < 4; q++) {
        xv[4 * q + 0] = __shfl_sync(0xffffffffu, o.x, baseq + q);
        xv[4 * q + 1] = __shfl_sync(0xffffffffu, o.y, baseq + q);
        xv[4 * q + 2] = __shfl_sync(0xffffffffu, o.z, baseq + q);
        xv[4 * q + 3] = __shfl_sync(0xffffffffu, o.w, baseq + q);
    }
    float acc8[8] = {};
#pragma unroll
    for (int k = 0; k < 16; k++) {
        const float* wr = &W2s[k * 32 + 8 * tg];
        float4 wa = *(const float4*)wr;
        float4 wb = *(const float4*)(wr + 4);
        acc8[0] += xv[k] * wa.x; acc8[1] += xv[k] * wa.y;
        acc8[2] += xv[k] * wa.z; acc8[3] += xv[k] * wa.w;
        acc8[4] += xv[k] * wb.x; acc8[5] += xv[k] * wb.y;
        acc8[6] += xv[k] * wb.z; acc8[7] += xv[k] * wb.w;
    }
    if (valid) {
        *(float4*)&h2out[n * 32 + 8 * tg]     = make_float4(acc8[0], acc8[1], acc8[2], acc8[3]);
        *(float4*)&h2out[n * 32 + 8 * tg + 4] = make_float4(acc8[4], acc8[5], acc8[6], acc8[7]);
    }
}

// ---------------- GCN aggregate (generic, optional fp16 copy out) ----------------
template<int C>
__global__ void gcn_agg_kernel(const float* __restrict__ h, const float* __restrict__ dinv,
                               const int* __restrict__ rowptr, const int* __restrict__ csr,
                               const float* __restrict__ bias, float* __restrict__ out,
                               __half* __restrict__ outb) {
    constexpr int TPN = C / 4;
    int gtid = blockIdx.x * blockDim.x + threadIdx.x;
    int n = gtid / TPN;
    int ch = 4 * (gtid % TPN);
    if (n >= NN) return;
    int r0 = rowptr[n], r1 = rowptr[n + 1];
    const float* hb = h + ch;
    ull a0 = 0ull, a1 = 0ull;
    for (int j = r0; j < r1; j++) {
        int s = csr[j];
        ull dv2 = pack2(dinv[s]);
        F4U hv; hv.f = *(const float4*)(hb + s * C);
        a0 = fma2(hv.u[0], dv2, a0);
        a1 = fma2(hv.u[1], dv2, a1);
    }
    float dn = dinv[n];
    float2 r01 = unpack2(a0), r23 = unpack2(a1);
    float4 b = *(const float4*)&bias[ch];
    float4 o;
    o.x = fmaxf(r01.x * dn + b.x, 0.f);
    o.y = fmaxf(r01.y * dn + b.y, 0.f);
    o.z = fmaxf(r23.x * dn + b.z, 0.f);
    o.w = fmaxf(r23.y * dn + b.w, 0.f);
    *(float4*)&out[n * C + ch] = o;
    if (outb) {
        __half2 p0 = __floats2half2_rn(o.x, o.y);
        __half2 p1 = __floats2half2_rn(o.z, o.w);
        uint2 u; u.x = *(uint32_t*)&p0; u.y = *(uint32_t*)&p1;
        *(uint2*)&outb[n * C + ch] = u;
    }
}

// ---------------- GAT aggregation: fused softmax, fp16 in/out ----------------
template<int H>
__global__ __launch_bounds__(128) void gat_agg_kernel(
        const __half* __restrict__ h, const float* __restrict__ asrc,
        const float* __restrict__ adst, const int* __restrict__ rowptr,
        const int* __restrict__ csr, const float* __restrict__ bias,
        __half* __restrict__ outb) {
    constexpr int HC = H * 32;
    constexpr int TPN = HC / 4;
    constexpr int NPB = 128 / TPN;
    constexpr int CH = 32;
    __shared__ float2 al_sh[NPB][CH * H];
    __shared__ int off_sh[NPB][CH];
    __shared__ float ad_sh[NPB][H];
    __shared__ int r0_sh[NPB];
    __shared__ int cnt_sh[NPB];
    __shared__ int mx_sh;

    int tid = threadIdx.x;
    int g = tid / TPN, tg = tid % TPN;
    int n = blockIdx.x * NPB + g;
    if (tid == 0) mx_sh = 0;
    if (tg < H) ad_sh[g][tg] = adst[n * H + tg];
    if (tg == 0) {
        int r0 = rowptr[n], r1 = rowptr[n + 1];
        r0_sh[g] = r0;
        cnt_sh[g] = r1 - r0;
    }
    __syncthreads();
    if (tg == 0) atomicMax(&mx_sh, cnt_sh[g]);
    __syncthreads();
    int cnt = cnt_sh[g], r0 = r0_sh[g];
    int nch = (mx_sh + CH - 1) / CH;
    int ch0 = 4 * tg;
    int hd = tg >> 3;
    const __half* hb = h + ch0;
    ull a0 = 0ull, a1 = 0ull;
    float den = 0.f;

    for (int c = 0; c < nch; c++) {
        int base = c * CH;
        int cc = min(CH, cnt - base);
#pragma unroll
        for (int it = 0; it < CH * H / TPN; it++) {
            int task = tg + it * TPN;
            int e = task / H;
            int hh = task - e * H;
            if (e < cc) {
                int j = r0 + base + e;
                int src = csr[j];
                float el = asrc[src * H + hh] + ad_sh[g][hh];
                el = fmaxf(el, NEG_SLOPE * el);
                float ev = __expf(el);
                al_sh[g][task] = make_float2(ev, ev);
                if (hh == 0) off_sh[g][e] = src * HC;
            }
        }
        __syncthreads();
        int e = 0;
        for (; e + 4 <= cc; e += 4) {
            int o0 = off_sh[g][e], o1 = off_sh[g][e + 1], o2 = off_sh[g][e + 2], o3 = off_sh[g][e + 3];
            F2U A0, A1, A2, A3;
            A0.f = al_sh[g][(e + 0) * H + hd];
            A1.f = al_sh[g][(e + 1) * H + hd];
            A2.f = al_sh[g][(e + 2) * H + hd];
            A3.f = al_sh[g][(e + 3) * H + hd];
            den += A0.f.x + A1.f.x + A2.f.x + A3.f.x;
            uint2 v0 = *(const uint2*)(hb + o0);
            uint2 v1 = *(const uint2*)(hb + o1);
            uint2 v2 = *(const uint2*)(hb + o2);
            uint2 v3 = *(const uint2*)(hb + o3);
            F2U f;
            f.f = __half22float2(*(__half2*)&v0.x); a0 = fma2(f.u, A0.u, a0);
            f.f = __half22float2(*(__half2*)&v0.y); a1 = fma2(f.u, A0.u, a1);
            f.f = __half22float2(*(__half2*)&v1.x); a0 = fma2(f.u, A1.u, a0);
            f.f = __half22float2(*(__half2*)&v1.y); a1 = fma2(f.u, A1.u, a1);
            f.f = __half22float2(*(__half2*)&v2.x); a0 = fma2(f.u, A2.u, a0);
            f.f = __half22float2(*(__half2*)&v2.y); a1 = fma2(f.u, A2.u, a1);
            f.f = __half22float2(*(__half2*)&v3.x); a0 = fma2(f.u, A3.u, a0);
            f.f = __half22float2(*(__half2*)&v3.y); a1 = fma2(f.u, A3.u, a1);
        }
        for (; e < cc; e++) {
            int o = off_sh[g][e];
            F2U A; A.f = al_sh[g][e * H + hd];
            den += A.f.x;
            uint2 v = *(const uint2*)(hb + o);
            F2U f;
            f.f = __half22float2(*(__half2*)&v.x); a0 = fma2(f.u, A.u, a0);
            f.f = __half22float2(*(__half2*)&v.y); a1 = fma2(f.u, A.u, a1);
        }
        __syncthreads();
    }
    float invd = 1.f / den;
    float2 r01 = unpack2(a0), r23 = unpack2(a1);
    float4 b = *(const float4*)&bias[ch0];
    float4 o;
    o.x = fmaxf(r01.x * invd + b.x, 0.f);
    o.y = fmaxf(r01.y * invd + b.y, 0.f);
    o.z = fmaxf(r23.x * invd + b.z, 0.f);
    o.w = fmaxf(r23.y * invd + b.w, 0.f);
    __half2 p0 = __floats2half2_rn(o.x, o.y);
    __half2 p1 = __floats2half2_rn(o.z, o.w);
    uint2 u; u.x = *(uint32_t*)&p0; u.y = *(uint32_t*)&p1;
    *(uint2*)&outb[n * HC + ch0] = u;
}

// ---------------- pooling partials: fp32 source ----------------
template<int NF4>
__global__ void pool_part_kernel(const float* __restrict__ src, int obase, int qy_total,
                                 const int* __restrict__ gstart, float* __restrict__ pool) {
    constexpr int SPB = 128 / NF4;
    int g = blockIdx.x;
    int q = blockIdx.y * SPB + threadIdx.x / NF4;
    int f = threadIdx.x % NF4;
    int slices = qy_total * SPB;
    int s = gstart[g], e = gstart[g + 1];
    int len = e - s;
    int n0 = s + (int)((long long)len * q / slices);
    int n1 = s + (int)((long long)len * (q + 1) / slices);
    ull a0 = 0ull, a1 = 0ull;
    int stride = NF4 * 4;
    for (int n = n0; n < n1; n++) {
        F4U v; v.f = *(const float4*)&src[(size_t)n * stride + 4 * f];
        a0 = add2(a0, v.u[0]);
        a1 = add2(a1, v.u[1]);
    }
    float2 r01 = unpack2(a0), r23 = unpack2(a1);
    float* dst = &pool[g * 432 + obase + 4 * f];
    atomicAdd(dst + 0, r01.x);
    atomicAdd(dst + 1, r01.y);
    atomicAdd(dst + 2, r23.x);
    atomicAdd(dst + 3, r23.y);
}

// ---------------- pooling partials: fp16 source ----------------
template<int NF4>
__global__ void pool_parth_kernel(const __half* __restrict__ src, int obase, int qy_total,
                                  const int* __restrict__ gstart, float* __restrict__ pool) {
    constexpr int SPB = 128 / NF4;
    int g = blockIdx.x;
    int q = blockIdx.y * SPB + threadIdx.x / NF4;
    int f = threadIdx.x % NF4;
    int slices = qy_total * SPB;
    int s = gstart[g], e = gstart[g + 1];
    int len = e - s;
    int n0 = s + (int)((long long)len * q / slices);
    int n1 = s + (int)((long long)len * (q + 1) / slices);
    ull a0 = 0ull, a1 = 0ull;
    int stride = NF4 * 4;
    for (int n = n0; n < n1; n++) {
        uint2 v = *(const uint2*)&src[(size_t)n * stride + 4 * f];
        F2U f0, f1;
        f0.f = __half22float2(*(__half2*)&v.x);
        f1.f = __half22float2(*(__half2*)&v.y);
        a0 = add2(a0, f0.u);
        a1 = add2(a1, f1.u);
    }
    float2 r01 = unpack2(a0), r23 = unpack2(a1);
    float* dst = &pool[g * 432 + obase + 4 * f];
    atomicAdd(dst + 0, r01.x);
    atomicAdd(dst + 1, r01.y);
    atomicAdd(dst + 2, r23.x);
    atomicAdd(dst + 3, r23.y);
}

// ---------------- final MLP ----------------
__global__ void fc_kernel(const float* __restrict__ pool, const int* __restrict__ gstart,
                          const float* __restrict__ W1, const float* __restrict__ b1,
                          const float* __restrict__ W2, const float* __restrict__ b2,
                          float* __restrict__ out) {
    int g = blockIdx.x, t = threadIdx.x;
    __shared__ float xp[432];
    __shared__ float ws[4];
    float cntf = (float)(gstart[g + 1] - gstart[g]);
    float invc = 1.f / fmaxf(cntf, 1.f);
    for (int i = t; i < 432; i += 128) xp[i] = pool[g * 432 + i] * invc;
    __syncthreads();
    float acc = b1[t];
    for (int i = 0; i < 432; i++) acc += xp[i] * W1[i * 128 + t];
    acc = fmaxf(acc, 0.f);
    float v = acc * W2[t];
#pragma unroll
    for (int o = 16; o; o >>= 1) v += __shfl_xor_sync(0xffffffffu, v, o);
    if ((t & 31) == 0) ws[t >> 5] = v;
    __syncthreads();
    if (t == 0) out[g] = ws[0] + ws[1] + ws[2] + ws[3] + b2[0];
}

// ---------------- launch ----------------
extern "C" void kernel_launch(void* const* d_in, const int* in_sizes, int n_in,
                              void* d_out, int out_size) {
    const float* x    = (const float*)d_in[0];
    const int*   ei   = (const int*)d_in[1];
    const int*   batch= (const int*)d_in[2];
    const float* W1   = (const float*)d_in[3];
    const float* b1   = (const float*)d_in[4];
    const float* W2   = (const float*)d_in[5];
    const float* b2   = (const float*)d_in[6];
    const float* W3   = (const float*)d_in[7];
    const float* as3  = (const float*)d_in[8];
    const float* ad3  = (const float*)d_in[9];
    const float* b3   = (const float*)d_in[10];
    const float* W4   = (const float*)d_in[11];
    const float* as4  = (const float*)d_in[12];
    const float* ad4  = (const float*)d_in[13];
    const float* b4   = (const float*)d_in[14];
    const float* Wfc1 = (const float*)d_in[15];
    const float* bfc1 = (const float*)d_in[16];
    const float* Wfc2 = (const float*)d_in[17];
    const float* bfc2 = (const float*)d_in[18];
    float* out = (float*)d_out;

    constexpr int SMEM3 = 64 * 80 + 128 * 80 + 2 * 4 * 32 * 4;     // 16384
    constexpr int SMEM4 = 64 * 272 + 256 * 272 + 2 * 8 * 32 * 4;   // 89088

    static float *p_x1 = nullptr, *p_x2, *p_h, *p_h2, *p_asrc, *p_adst, *p_dinv, *p_pool;
    static __half *p_hb, *p_x2b, *p_x3b, *p_x4b, *p_w3t, *p_w4t;
    static int *p_counts, *p_rank, *p_bsum, *p_rowptr, *p_csr, *p_gstart;
    static cudaStream_t s1, s2;
    static cudaEvent_t evRoot, evG1, evW, evX1, evX2, evX3, evX4, evFC;
    if (!p_x1) {
        cudaGetSymbolAddress((void**)&p_x1, g_x1);
        cudaGetSymbolAddress((void**)&p_x2, g_x2);
        cudaGetSymbolAddress((void**)&p_h, g_h);
        cudaGetSymbolAddress((void**)&p_h2, g_h2);
        cudaGetSymbolAddress((void**)&p_hb, g_hb);
        cudaGetSymbolAddress((void**)&p_x2b, g_x2b);
        cudaGetSymbolAddress((void**)&p_x3b, g_x3b);
        cudaGetSymbolAddress((void**)&p_x4b, g_x4b);
        cudaGetSymbolAddress((void**)&p_w3t, g_w3t);
        cudaGetSymbolAddress((void**)&p_w4t, g_w4t);
        cudaGetSymbolAddress((void**)&p_asrc, g_asrc);
        cudaGetSymbolAddress((void**)&p_adst, g_adst);
        cudaGetSymbolAddress((void**)&p_dinv, g_dinv);
        cudaGetSymbolAddress((void**)&p_pool, g_pool);
        cudaGetSymbolAddress((void**)&p_counts, g_counts);
        cudaGetSymbolAddress((void**)&p_rank, g_rank);
        cudaGetSymbolAddress((void**)&p_bsum, g_bsum);
        cudaGetSymbolAddress((void**)&p_rowptr, g_rowptr);
        cudaGetSymbolAddress((void**)&p_csr, g_csr_src);
        cudaGetSymbolAddress((void**)&p_gstart, g_gstart);
        cudaStreamCreateWithFlags(&s1, cudaStreamNonBlocking);
        cudaStreamCreateWithFlags(&s2, cudaStreamNonBlocking);
        cudaEventCreateWithFlags(&evRoot, cudaEventDisableTiming);
        cudaEventCreateWithFlags(&evG1, cudaEventDisableTiming);
        cudaEventCreateWithFlags(&evW, cudaEventDisableTiming);
        cudaEventCreateWithFlags(&evX1, cudaEventDisableTiming);
        cudaEventCreateWithFlags(&evX2, cudaEventDisableTiming);
        cudaEventCreateWithFlags(&evX3, cudaEventDisableTiming);
        cudaEventCreateWithFlags(&evX4, cudaEventDisableTiming);
        cudaEventCreateWithFlags(&evFC, cudaEventDisableTiming);
        cudaFuncSetAttribute((const void*)gemm_mma_kernel<32, 128>,
                             cudaFuncAttributeMaxDynamicSharedMemorySize, SMEM3);
        cudaFuncSetAttribute((const void*)gemm_mma_kernel<128, 256>,
                             cudaFuncAttributeMaxDynamicSharedMemorySize, SMEM4);
    }

    // fork
    cudaEventRecord(evRoot, 0);
    cudaStreamWaitEvent(s1, evRoot, 0);
    cudaStreamWaitEvent(s2, evRoot, 0);

    // s0: CSR chain (rank-based, atomic-free fill, 4 edges/thread)
    cudaMemsetAsync(p_counts, 0, NN * sizeof(int), 0);
    count_edges_kernel<<<(ETOT / 4 + 255) / 256, 256>>>(ei, p_counts, p_rank);
    scan_reduce_kernel<<<RB, 1024>>>(p_counts, p_bsum);
    scan_apply_kernel<<<RB, 1024>>>(p_counts, p_bsum, p_rowptr, p_dinv);
    fill_csr_kernel<<<(ETOT / 4 + 255) / 256, 256>>>(ei, p_rowptr, p_rank, p_csr);

    // s1: gstart + pool init + W transposes (independent)
    gstart_kernel<<<(NN + 255) / 256, 256, 0, s1>>>(batch, p_gstart);
    cudaMemsetAsync(p_pool, 0, GG * 432 * sizeof(float), s1);
    wt_kernel<32, 128><<<(128 * 32 + 255) / 256, 256, 0, s1>>>(W3, p_w3t);
    wt_kernel<128, 256><<<(256 * 128 + 255) / 256, 256, 0, s1>>>(W4, p_w4t);
    cudaEventRecord(evW, s1);

    // s2: GEMM1 (independent of CSR)
    {
        dim3 b(4, 16), g((NN + 63) / 64, 1);
        gemm_small_kernel<128, 16><<<g, b, 0, s2>>>(x, W1, p_h);
        cudaEventRecord(evG1, s2);
    }

    // GCN layer 1 aggregate + fused x1@W2 GEMM
    cudaStreamWaitEvent(0, evG1, 0);
    gcn1_fused_kernel<<<(NN * 4 + 255) / 256, 256>>>(p_h, p_dinv, p_rowptr, p_csr, b1, W2,
                                                     p_x1, p_h2);
    cudaEventRecord(evX1, 0);
    cudaStreamWaitEvent(s1, evX1, 0);
    pool_part_kernel<4><<<dim3(GG, 1), 128, 0, s1>>>(p_x1, 0, 1, p_gstart, p_pool);

    // GCN layer 2 aggregate
    gcn_agg_kernel<32><<<(NN * 8 + 255) / 256, 256>>>(p_h2, p_dinv, p_rowptr, p_csr, b2, p_x2, p_x2b);
    cudaEventRecord(evX2, 0);
    cudaStreamWaitEvent(s1, evX2, 0);
    pool_part_kernel<8><<<dim3(GG, 1), 128, 0, s1>>>(p_x2, 16, 1, p_gstart, p_pool);

    // GAT layer 3 (32 -> 4x32): HMMA + fused-softmax aggregation (fp16 out)
    cudaStreamWaitEvent(0, evW, 0);
    gemm_mma_kernel<32, 128><<<(NN + 63) / 64, 256, SMEM3>>>(p_x2b, p_w3t, as3, ad3,
                                                             p_hb, p_asrc, p_adst);
    gat_agg_kernel<4><<<NN / 4, 128>>>(p_hb, p_asrc, p_adst, p_rowptr, p_csr, b3, p_x3b);
    cudaEventRecord(evX3, 0);
    cudaStreamWaitEvent(s1, evX3, 0);
    pool_parth_kernel<32><<<dim3(GG, 2), 128, 0, s1>>>(p_x3b, 48, 2, p_gstart, p_pool);

    // GAT layer 4 (128 -> 8x32): HMMA + fused-softmax aggregation (fp16 out)
    gemm_mma_kernel<128, 256><<<(NN + 63) / 64, 256, SMEM4>>>(p_x3b, p_w4t, as4, ad4,
                                                              p_hb, p_asrc, p_adst);
    gat_agg_kernel<8><<<NN / 2, 128>>>(p_hb, p_asrc, p_adst, p_rowptr, p_csr, b4, p_x4b);
    cudaEventRecord(evX4, 0);
    cudaStreamWaitEvent(s1, evX4, 0);
    pool_parth_kernel<64><<<dim3(GG, 4), 128, 0, s1>>>(p_x4b, 176, 4, p_gstart, p_pool);

    // FC on s1
    fc_kernel<<<GG, 128, 0, s1>>>(p_pool, p_gstart, Wfc1, bfc1, Wfc2, bfc2, out);
    cudaEventRecord(evFC, s1);
    cudaStreamWaitEvent(0, evFC, 0);
}

// round 15
// speedup vs baseline: 1.0395x; 1.0395x over previous
#include <cuda_runtime.h>
#include <cuda_fp16.h>
#include <cstdint>

#define NN 50000
#define EE 800000
#define ETOT (EE + NN)
#define GG 128
#define NEG_SLOPE 0.2f
#define RB 49   // ceil(NN/1024)

typedef unsigned long long ull;

union F4U { float4 f; ull u[2]; };
union F2U { float2 f; ull u; };

__device__ __forceinline__ ull fma2(ull a, ull b, ull c) {
    ull d; asm("fma.rn.f32x2 %0,%1,%2,%3;" : "=l"(d) : "l"(a), "l"(b), "l"(c)); return d;
}
__device__ __forceinline__ ull add2(ull a, ull b) {
    ull d; asm("add.rn.f32x2 %0,%1,%2;" : "=l"(d) : "l"(a), "l"(b)); return d;
}
__device__ __forceinline__ ull pack2(float x) {
    F2U t; t.f = make_float2(x, x); return t.u;
}
__device__ __forceinline__ float2 unpack2(ull v) { F2U t; t.u = v; return t.f; }

__device__ __forceinline__ uint32_t smem_u32(const void* p) {
    uint32_t a;
    asm("{ .reg .u64 t; cvta.to.shared.u64 t, %1; cvt.u32.u64 %0, t; }" : "=r"(a) : "l"(p));
    return a;
}
__device__ __forceinline__ void ldsm4(uint32_t& r0, uint32_t& r1, uint32_t& r2, uint32_t& r3,
                                      uint32_t addr) {
    asm volatile("ldmatrix.sync.aligned.m8n8.x4.shared.b16 {%0,%1,%2,%3}, [%4];"
                 : "=r"(r0), "=r"(r1), "=r"(r2), "=r"(r3) : "r"(addr));
}
__device__ __forceinline__ void mma16816(float* c, uint32_t a0, uint32_t a1, uint32_t a2,
                                         uint32_t a3, uint32_t b0, uint32_t b1) {
    asm volatile(
        "mma.sync.aligned.m16n8k16.row.col.f32.f16.f16.f32 "
        "{%0,%1,%2,%3},{%4,%5,%6,%7},{%8,%9},{%0,%1,%2,%3};"
        : "+f"(c[0]), "+f"(c[1]), "+f"(c[2]), "+f"(c[3])
        : "r"(a0), "r"(a1), "r"(a2), "r"(a3), "r"(b0), "r"(b1));
}

// ---------------- scratch ----------------
__device__ float g_x1[NN * 16];
__device__ float g_x2[NN * 32];
__device__ float g_h [NN * 16];
__device__ float g_h2[NN * 32];
__device__ __half g_hb[NN * 256];
__device__ __half g_x2b[NN * 32];
__device__ __half g_x3b[NN * 128];
__device__ __half g_x4b[NN * 256];
__device__ __half g_w3t[128 * 32];
__device__ __half g_w4t[256 * 128];
__device__ float g_asrc[NN * 8];
__device__ float g_adst[NN * 8];
__device__ float g_dinv[NN];
__device__ int   g_counts[NN];          // statically zero; every call restores zeros
__device__ int   g_rank[EE];
__device__ int   g_bsum[RB];
__device__ int   g_rowptr[NN + 1];
__device__ int   g_csr_src[ETOT];
__device__ int   g_gstart[GG + 1];
__device__ float g_pool[GG * 432];

// ---------------- CSR build ----------------
// count real edges only; rank = position within dst bucket (self-loop gets last slot)
__global__ void count_edges_kernel(const int* __restrict__ ei, int* __restrict__ counts,
                                   int* __restrict__ rank) {
    int e = blockIdx.x * blockDim.x + threadIdx.x;
    if (e >= EE) return;
    int dst = ei[EE + e];
    rank[e] = atomicAdd(&counts[dst], 1);
}

__global__ void scan_reduce_kernel(const int* __restrict__ counts, int* __restrict__ bsum) {
    __shared__ int ws[32];
    int i = blockIdx.x * 1024 + threadIdx.x;
    int v = (i < NN) ? counts[i] : 0;
    int lane = threadIdx.x & 31, w = threadIdx.x >> 5;
#pragma unroll
    for (int o = 16; o; o >>= 1) v += __shfl_xor_sync(0xffffffffu, v, o);
    if (lane == 0) ws[w] = v;
    __syncthreads();
    if (w == 0) {
        int s = ws[lane];
#pragma unroll
        for (int o = 16; o; o >>= 1) s += __shfl_xor_sync(0xffffffffu, s, o);
        if (lane == 0) bsum[blockIdx.x] = s;
    }
}

// scan_apply: rowptr[i+1] = scan(cnt) + i + 1 (each node has one self-loop);
// writes the self-loop CSR entry (last slot of the bucket), computes dinv,
// and re-zeros counts for the next graph replay.
__global__ void scan_apply_kernel(int* __restrict__ counts, const int* __restrict__ bsum,
                                  int* __restrict__ rowptr, float* __restrict__ dinv,
                                  int* __restrict__ csr) {
    __shared__ int ws[32];
    __shared__ int boff_sh;
    int i = blockIdx.x * 1024 + threadIdx.x;
    int cnt = (i < NN) ? counts[i] : 0;
    int lane = threadIdx.x & 31, w = threadIdx.x >> 5;
    int v = cnt;
#pragma unroll
    for (int o = 1; o < 32; o <<= 1) {
        int u = __shfl_up_sync(0xffffffffu, v, o);
        if (lane >= o) v += u;
    }
    if (lane == 31) ws[w] = v;
    __syncthreads();
    if (w == 0) {
        int s = ws[lane];
#pragma unroll
        for (int o = 1; o < 32; o <<= 1) {
            int u = __shfl_up_sync(0xffffffffu, s, o);
            if (lane >= o) s += u;
        }
        ws[lane] = s;
    }
    if (w == 1) {
        int lim = (int)blockIdx.x < RB ? (int)blockIdx.x : RB;
        int v2 = (lane < lim) ? bsum[lane] : 0;
        if (lane + 32 < lim) v2 += bsum[lane + 32];
#pragma unroll
        for (int o = 16; o; o >>= 1) v2 += __shfl_xor_sync(0xffffffffu, v2, o);
        if (lane == 0) boff_sh = v2;
    }
    __syncthreads();
    int incl = v + (w ? ws[w - 1] : 0) + boff_sh;   // inclusive scan of real counts
    if (i < NN) {
        rowptr[i + 1] = incl + i + 1;               // + (i+1) self-loops
        csr[incl + i] = i;                          // self-loop at last slot
        dinv[i] = rsqrtf((float)(cnt + 1));
        counts[i] = 0;                              // reset for next replay
    }
    if (i == 0) rowptr[0] = 0;
}

// atomic-free fill of real edges: pos = rowptr[dst] + rank[e]
__global__ void fill_csr_kernel(const int* __restrict__ ei, const int* __restrict__ rowptr,
                                const int* __restrict__ rank, int* __restrict__ csr) {
    int e = blockIdx.x * blockDim.x + threadIdx.x;
    if (e >= EE) return;
    int src = ei[e];
    int dst = ei[EE + e];
    csr[rowptr[dst] + rank[e]] = src;
}

__global__ void gstart_kernel(const int* __restrict__ batch, int* __restrict__ gstart) {
    int n = blockIdx.x * blockDim.x + threadIdx.x;
    if (n >= NN) return;
    int b = batch[n];
    if (n == 0) { for (int g = 0; g <= b; g++) gstart[g] = 0; }
    else {
        int pb = batch[n - 1];
        for (int g = pb + 1; g <= b; g++) gstart[g] = n;
    }
    if (n == NN - 1) { for (int g = b + 1; g <= GG; g++) gstart[g] = NN; }
}

// ---- W transpose to fp16 [NOUT][KEL] ----
template<int KEL, int NOUT>
__global__ void wt_kernel(const float* __restrict__ W, __half* __restrict__ Wt) {
    int idx = blockIdx.x * 256 + threadIdx.x;
    if (idx >= KEL * NOUT) return;
    int n = idx / KEL, k = idx % KEL;
    Wt[idx] = __float2half(W[k * NOUT + n]);
}

// ---------------- small GEMM (fp32) ----------------
template<int K, int M>
__global__ void gemm_small_kernel(const float* __restrict__ X, const float* __restrict__ W,
                                  float* __restrict__ Y) {
    constexpr int CT = M;
    constexpr int KC = (K < 64) ? K : 64;
    constexpr int TX = CT / 4;
    constexpr int NT = TX * 16;
    constexpr int RP = 68;
    __shared__ float Xs[KC * RP];
    __shared__ float Ws[KC * CT];
    int row0 = blockIdx.x * 64;
    int tid = threadIdx.y * TX + threadIdx.x;
    float acc[4][4] = {};
    for (int k0 = 0; k0 < K; k0 += KC) {
        for (int idx = tid; idx < 64 * KC; idx += NT) {
            int r = idx / KC, k = idx % KC;
            int gr = row0 + r;
            Xs[k * RP + r] = (gr < NN) ? X[gr * K + k0 + k] : 0.f;
        }
        for (int idx = tid; idx < KC * CT; idx += NT) {
            int k = idx / CT, c = idx % CT;
            Ws[k * CT + c] = W[(k0 + k) * M + c];
        }
        __syncthreads();
#pragma unroll 8
        for (int k = 0; k < KC; k++) {
            float4 xv = *(const float4*)&Xs[k * RP + 4 * threadIdx.y];
            float4 wv = *(const float4*)&Ws[k * CT + 4 * threadIdx.x];
            float xa[4] = {xv.x, xv.y, xv.z, xv.w};
            float wa[4] = {wv.x, wv.y, wv.z, wv.w};
#pragma unroll
            for (int i = 0; i < 4; i++)
#pragma unroll
                for (int j = 0; j < 4; j++)
                    acc[i][j] += xa[i] * wa[j];
        }
        __syncthreads();
    }
#pragma unroll
    for (int i = 0; i < 4; i++) {
        int r = row0 + 4 * threadIdx.y + i;
        if (r < NN) {
            float4 o = make_float4(acc[i][0], acc[i][1], acc[i][2], acc[i][3]);
            *(float4*)&Y[r * M + 4 * threadIdx.x] = o;
        }
    }
}

// ---------------- HMMA GEMM: h = X@W (fp16 in/out), fused attention coefficients ----------------
template<int KEL, int NOUT>
__global__ __launch_bounds__(256) void gemm_mma_kernel(
        const __half* __restrict__ Xb, const __half* __restrict__ Wt,
        const float* __restrict__ att_s, const float* __restrict__ att_d,
        __half* __restrict__ Yb, float* __restrict__ asrc, float* __restrict__ adst) {
    constexpr int H = NOUT / 32;
    constexpr int KP = KEL + 8;
    constexpr int KPB = KP * 2;
    constexpr int A_OFF = 0;
    constexpr int B_OFF = 64 * KPB;
    constexpr int ATT_OFF = B_OFF + NOUT * KPB;
    constexpr int AU = KEL / 8;
    constexpr int NTILES = NOUT / 16;

    extern __shared__ char smem[];
    uint32_t sb = smem_u32(smem);
    int tid = threadIdx.x, w = tid >> 5, lane = tid & 31;
    int row0 = blockIdx.x * 64;

    for (int idx = tid; idx < 64 * AU; idx += 256) {
        int r = idx / AU, u = idx % AU;
        int gr = row0 + r;
        uint4 v = make_uint4(0, 0, 0, 0);
        if (gr < NN) v = *(const uint4*)&Xb[(size_t)gr * KEL + u * 8];
        *(uint4*)(smem + A_OFF + r * KPB + u * 16) = v;
    }
    for (int idx = tid; idx < NOUT * AU; idx += 256) {
        int r = idx / AU, u = idx % AU;
        *(uint4*)(smem + B_OFF + r * KPB + u * 16) = *(const uint4*)&Wt[r * KEL + u * 8];
    }
    float* att_sh = (float*)(smem + ATT_OFF);
    for (int idx = tid; idx < 2 * H * 32; idx += 256)
        att_sh[idx] = (idx < H * 32) ? att_s[idx] : att_d[idx - H * 32];
    __syncthreads();

    int wr = w >> 1, wc = w & 1;
    float acc[NTILES][4];
#pragma unroll
    for (int t = 0; t < NTILES; t++)
#pragma unroll
        for (int q = 0; q < 4; q++) acc[t][q] = 0.f;

    uint32_t aaddr = sb + A_OFF + (wr * 16 + (lane & 15)) * KPB + ((lane >> 4) << 4);
    uint32_t baddr = sb + B_OFF +
                     (wc * (NOUT / 2) + (lane & 7) + ((lane >> 4) << 3)) * KPB +
                     (((lane >> 3) & 1) << 4);
#pragma unroll
    for (int ks = 0; ks < KEL / 16; ks++) {
        uint32_t a0, a1, a2, a3;
        ldsm4(a0, a1, a2, a3, aaddr + ks * 32);
#pragma unroll
        for (int p = 0; p < NTILES / 2; p++) {
            uint32_t b0, b1, b2, b3;
            ldsm4(b0, b1, b2, b3, baddr + p * 16 * KPB + ks * 32);
            mma16816(acc[2 * p],     a0, a1, a2, a3, b0, b1);
            mma16816(acc[2 * p + 1], a0, a1, a2, a3, b2, b3);
        }
    }

    int g = lane >> 2;
    int r0g = row0 + wr * 16 + g;
    int r1g = r0g + 8;
    constexpr int HLOC = H / 2;
#pragma unroll
    for (int hh = 0; hh < HLOC; hh++) {
        int ghead = wc * HLOC + hh;
        float s0 = 0.f, d0 = 0.f, s1 = 0.f, d1 = 0.f;
#pragma unroll
        for (int t4 = 0; t4 < 4; t4++) {
            int t = hh * 4 + t4;
            int cih = t4 * 8 + (lane & 3) * 2;
            float aS0 = att_sh[ghead * 32 + cih];
            float aS1 = att_sh[ghead * 32 + cih + 1];
            float aD0 = att_sh[H * 32 + ghead * 32 + cih];
            float aD1 = att_sh[H * 32 + ghead * 32 + cih + 1];
            s0 += acc[t][0] * aS0 + acc[t][1] * aS1;
            d0 += acc[t][0] * aD0 + acc[t][1] * aD1;
            s1 += acc[t][2] * aS0 + acc[t][3] * aS1;
            d1 += acc[t][2] * aD0 + acc[t][3] * aD1;
        }
#pragma unroll
        for (int o = 1; o <= 2; o <<= 1) {
            s0 += __shfl_xor_sync(0xffffffffu, s0, o);
            d0 += __shfl_xor_sync(0xffffffffu, d0, o);
            s1 += __shfl_xor_sync(0xffffffffu, s1, o);
            d1 += __shfl_xor_sync(0xffffffffu, d1, o);
        }
        if ((lane & 3) == 0) {
            if (r0g < NN) { asrc[r0g * H + ghead] = s0; adst[r0g * H + ghead] = d0; }
            if (r1g < NN) { asrc[r1g * H + ghead] = s1; adst[r1g * H + ghead] = d1; }
        }
    }
#pragma unroll
    for (int t = 0; t < NTILES; t++) {
        int col = wc * (NOUT / 2) + t * 8 + (lane & 3) * 2;
        if (r0g < NN) {
            __half2 h2 = __floats2half2_rn(acc[t][0], acc[t][1]);
            *(uint32_t*)&Yb[(size_t)r0g * NOUT + col] = *(uint32_t*)&h2;
        }
        if (r1g < NN) {
            __half2 h2 = __floats2half2_rn(acc[t][2], acc[t][3]);
            *(uint32_t*)&Yb[(size_t)r1g * NOUT + col] = *(uint32_t*)&h2;
        }
    }
}

// ---------------- GCN layer-1 aggregate + fused x1@W2 GEMM ----------------
__global__ __launch_bounds__(256) void gcn1_fused_kernel(
        const float* __restrict__ h, const float* __restrict__ dinv,
        const int* __restrict__ rowptr, const int* __restrict__ csr,
        const float* __restrict__ bias, const float* __restrict__ W2,
        float* __restrict__ x1out, float* __restrict__ h2out) {
    __shared__ float W2s[512];
    int tid = threadIdx.x;
    for (int idx = tid; idx < 512; idx += 256) W2s[idx] = W2[idx];
    __syncthreads();

    int gtid = blockIdx.x * 256 + tid;
    int n = gtid >> 2;
    int tg = tid & 3;
    int lane = tid & 31;
    bool valid = n < NN;
    int ch = 4 * tg;
    int r0 = 0, r1 = 0;
    if (valid) { r0 = rowptr[n]; r1 = rowptr[n + 1]; }
    const float* hb = h + ch;
    ull a0 = 0ull, a1 = 0ull;
    for (int j = r0; j < r1; j++) {
        int s = csr[j];
        ull dv2 = pack2(dinv[s]);
        F4U hv; hv.f = *(const float4*)(hb + s * 16);
        a0 = fma2(hv.u[0], dv2, a0);
        a1 = fma2(hv.u[1], dv2, a1);
    }
    float dn = valid ? dinv[n] : 0.f;
    float2 r01 = unpack2(a0), r23 = unpack2(a1);
    float4 b = *(const float4*)&bias[ch];
    float4 o;
    o.x = fmaxf(r01.x * dn + b.x, 0.f);
    o.y = fmaxf(r01.y * dn + b.y, 0.f);
    o.z = fmaxf(r23.x * dn + b.z, 0.f);
    o.w = fmaxf(r23.y * dn + b.w, 0.f);
    if (valid) *(float4*)&x1out[n * 16 + ch] = o;

    float xv[16];
    int baseq = lane & ~3;
#pragma unroll
    for (int q = 0; q < 4; q++) {
        xv[4 * q + 0] = __shfl_sync(0xffffffffu, o.x, baseq + q);
        xv[4 * q + 1] = __shfl_sync(0xffffffffu, o.y, baseq + q);
        xv[4 * q + 2] = __shfl_sync(0xffffffffu, o.z, baseq + q);
        xv[4 * q + 3] = __shfl_sync(0xffffffffu, o.w, baseq + q);
    }
    float acc8[8] = {};
#pragma unroll
    for (int k = 0; k < 16; k++) {
        const float* wr = &W2s[k * 32 + 8 * tg];
        float4 wa = *(const float4*)wr;
        float4 wb = *(const float4*)(wr + 4);
        acc8[0] += xv[k] * wa.x; acc8[1] += xv[k] * wa.y;
        acc8[2] += xv[k] * wa.z; acc8[3] += xv[k] * wa.w;
        acc8[4] += xv[k] * wb.x; acc8[5] += xv[k] * wb.y;
        acc8[6] += xv[k] * wb.z; acc8[7] += xv[k] * wb.w;
    }
    if (valid) {
        *(float4*)&h2out[n * 32 + 8 * tg]     = make_float4(acc8[0], acc8[1], acc8[2], acc8[3]);
        *(float4*)&h2out[n * 32 + 8 * tg + 4] = make_float4(acc8[4], acc8[5], acc8[6], acc8[7]);
    }
}

// ---------------- GCN aggregate (generic, optional fp16 copy out) ----------------
template<int C>
__global__ void gcn_agg_kernel(const float* __restrict__ h, const float* __restrict__ dinv,
                               const int* __restrict__ rowptr, const int* __restrict__ csr,
                               const float* __restrict__ bias, float* __restrict__ out,
                               __half* __restrict__ outb) {
    constexpr int TPN = C / 4;
    int gtid = blockIdx.x * blockDim.x + threadIdx.x;
    int n = gtid / TPN;
    int ch = 4 * (gtid % TPN);
    if (n >= NN) return;
    int r0 = rowptr[n], r1 = rowptr[n + 1];
    const float* hb = h + ch;
    ull a0 = 0ull, a1 = 0ull;
    for (int j = r0; j < r1; j++) {
        int s = csr[j];
        ull dv2 = pack2(dinv[s]);
        F4U hv; hv.f = *(const float4*)(hb + s * C);
        a0 = fma2(hv.u[0], dv2, a0);
        a1 = fma2(hv.u[1], dv2, a1);
    }
    float dn = dinv[n];
    float2 r01 = unpack2(a0), r23 = unpack2(a1);
    float4 b = *(const float4*)&bias[ch];
    float4 o;
    o.x = fmaxf(r01.x * dn + b.x, 0.f);
    o.y = fmaxf(r01.y * dn + b.y, 0.f);
    o.z = fmaxf(r23.x * dn + b.z, 0.f);
    o.w = fmaxf(r23.y * dn + b.w, 0.f);
    *(float4*)&out[n * C + ch] = o;
    if (outb) {
        __half2 p0 = __floats2half2_rn(o.x, o.y);
        __half2 p1 = __floats2half2_rn(o.z, o.w);
        uint2 u; u.x = *(uint32_t*)&p0; u.y = *(uint32_t*)&p1;
        *(uint2*)&outb[n * C + ch] = u;
    }
}

// ---------------- GAT aggregation: fused softmax, fp16 in/out ----------------
template<int H>
__global__ __launch_bounds__(128) void gat_agg_kernel(
        const __half* __restrict__ h, const float* __restrict__ asrc,
        const float* __restrict__ adst, const int* __restrict__ rowptr,
        const int* __restrict__ csr, const float* __restrict__ bias,
        __half* __restrict__ outb) {
    constexpr int HC = H * 32;
    constexpr int TPN = HC / 4;
    constexpr int NPB = 128 / TPN;
    constexpr int CH = 32;
    __shared__ float2 al_sh[NPB][CH * H];
    __shared__ int off_sh[NPB][CH];
    __shared__ float ad_sh[NPB][H];
    __shared__ int r0_sh[NPB];
    __shared__ int cnt_sh[NPB];
    __shared__ int mx_sh;

    int tid = threadIdx.x;
    int g = tid / TPN, tg = tid % TPN;
    int n = blockIdx.x * NPB + g;
    if (tid == 0) mx_sh = 0;
    if (tg < H) ad_sh[g][tg] = adst[n * H + tg];
    if (tg == 0) {
        int r0 = rowptr[n], r1 = rowptr[n + 1];
        r0_sh[g] = r0;
        cnt_sh[g] = r1 - r0;
    }
    __syncthreads();
    if (tg == 0) atomicMax(&mx_sh, cnt_sh[g]);
    __syncthreads();
    int cnt = cnt_sh[g], r0 = r0_sh[g];
    int nch = (mx_sh + CH - 1) / CH;
    int ch0 = 4 * tg;
    int hd = tg >> 3;
    const __half* hb = h + ch0;
    ull a0 = 0ull, a1 = 0ull;
    float den = 0.f;

    for (int c = 0; c < nch; c++) {
        int base = c * CH;
        int cc = min(CH, cnt - base);
#pragma unroll
        for (int it = 0; it < CH * H / TPN; it++) {
            int task = tg + it * TPN;
            int e = task / H;
            int hh = task - e * H;
            if (e < cc) {
                int j = r0 + base + e;
                int src = csr[j];
                float el = asrc[src * H + hh] + ad_sh[g][hh];
                el = fmaxf(el, NEG_SLOPE * el);
                float ev = __expf(el);
                al_sh[g][task] = make_float2(ev, ev);
                if (hh == 0) off_sh[g][e] = src * HC;
            }
        }
        __syncthreads();
        int e = 0;
        for (; e + 4 <= cc; e += 4) {
            int o0 = off_sh[g][e], o1 = off_sh[g][e + 1], o2 = off_sh[g][e + 2], o3 = off_sh[g][e + 3];
            F2U A0, A1, A2, A3;
            A0.f = al_sh[g][(e + 0) * H + hd];
            A1.f = al_sh[g][(e + 1) * H + hd];
            A2.f = al_sh[g][(e + 2) * H + hd];
            A3.f = al_sh[g][(e + 3) * H + hd];
            den += A0.f.x + A1.f.x + A2.f.x + A3.f.x;
            uint2 v0 = *(const uint2*)(hb + o0);
            uint2 v1 = *(const uint2*)(hb + o1);
            uint2 v2 = *(const uint2*)(hb + o2);
            uint2 v3 = *(const uint2*)(hb + o3);
            F2U f;
            f.f = __half22float2(*(__half2*)&v0.x); a0 = fma2(f.u, A0.u, a0);
            f.f = __half22float2(*(__half2*)&v0.y); a1 = fma2(f.u, A0.u, a1);
            f.f = __half22float2(*(__half2*)&v1.x); a0 = fma2(f.u, A1.u, a0);
            f.f = __half22float2(*(__half2*)&v1.y); a1 = fma2(f.u, A1.u, a1);
            f.f = __half22float2(*(__half2*)&v2.x); a0 = fma2(f.u, A2.u, a0);
            f.f = __half22float2(*(__half2*)&v2.y); a1 = fma2(f.u, A2.u, a1);
            f.f = __half22float2(*(__half2*)&v3.x); a0 = fma2(f.u, A3.u, a0);
            f.f = __half22float2(*(__half2*)&v3.y); a1 = fma2(f.u, A3.u, a1);
        }
        for (; e < cc; e++) {
            int o = off_sh[g][e];
            F2U A; A.f = al_sh[g][e * H + hd];
            den += A.f.x;
            uint2 v = *(const uint2*)(hb + o);
            F2U f;
            f.f = __half22float2(*(__half2*)&v.x); a0 = fma2(f.u, A.u, a0);
            f.f = __half22float2(*(__half2*)&v.y); a1 = fma2(f.u, A.u, a1);
        }
        __syncthreads();
    }
    float invd = 1.f / den;
    float2 r01 = unpack2(a0), r23 = unpack2(a1);
    float4 b = *(const float4*)&bias[ch0];
    float4 o;
    o.x = fmaxf(r01.x * invd + b.x, 0.f);
    o.y = fmaxf(r01.y * invd + b.y, 0.f);
    o.z = fmaxf(r23.x * invd + b.z, 0.f);
    o.w = fmaxf(r23.y * invd + b.w, 0.f);
    __half2 p0 = __floats2half2_rn(o.x, o.y);
    __half2 p1 = __floats2half2_rn(o.z, o.w);
    uint2 u; u.x = *(uint32_t*)&p0; u.y = *(uint32_t*)&p1;
    *(uint2*)&outb[n * HC + ch0] = u;
}

// ---------------- pooling partials: fp32 source ----------------
template<int NF4>
__global__ void pool_part_kernel(const float* __restrict__ src, int obase, int qy_total,
                                 const int* __restrict__ gstart, float* __restrict__ pool) {
    constexpr int SPB = 128 / NF4;
    int g = blockIdx.x;
    int q = blockIdx.y * SPB + threadIdx.x / NF4;
    int f = threadIdx.x % NF4;
    int slices = qy_total * SPB;
    int s = gstart[g], e = gstart[g + 1];
    int len = e - s;
    int n0 = s + (int)((long long)len * q / slices);
    int n1 = s + (int)((long long)len * (q + 1) / slices);
    ull a0 = 0ull, a1 = 0ull;
    int stride = NF4 * 4;
    for (int n = n0; n < n1; n++) {
        F4U v; v.f = *(const float4*)&src[(size_t)n * stride + 4 * f];
        a0 = add2(a0, v.u[0]);
        a1 = add2(a1, v.u[1]);
    }
    float2 r01 = unpack2(a0), r23 = unpack2(a1);
    float* dst = &pool[g * 432 + obase + 4 * f];
    atomicAdd(dst + 0, r01.x);
    atomicAdd(dst + 1, r01.y);
    atomicAdd(dst + 2, r23.x);
    atomicAdd(dst + 3, r23.y);
}

// ---------------- pooling partials: fp16 source ----------------
template<int NF4>
__global__ void pool_parth_kernel(const __half* __restrict__ src, int obase, int qy_total,
                                  const int* __restrict__ gstart, float* __restrict__ pool) {
    constexpr int SPB = 128 / NF4;
    int g = blockIdx.x;
    int q = blockIdx.y * SPB + threadIdx.x / NF4;
    int f = threadIdx.x % NF4;
    int slices = qy_total * SPB;
    int s = gstart[g], e = gstart[g + 1];
    int len = e - s;
    int n0 = s + (int)((long long)len * q / slices);
    int n1 = s + (int)((long long)len * (q + 1) / slices);
    ull a0 = 0ull, a1 = 0ull;
    int stride = NF4 * 4;
    for (int n = n0; n < n1; n++) {
        uint2 v = *(const uint2*)&src[(size_t)n * stride + 4 * f];
        F2U f0, f1;
        f0.f = __half22float2(*(__half2*)&v.x);
        f1.f = __half22float2(*(__half2*)&v.y);
        a0 = add2(a0, f0.u);
        a1 = add2(a1, f1.u);
    }
    float2 r01 = unpack2(a0), r23 = unpack2(a1);
    float* dst = &pool[g * 432 + obase + 4 * f];
    atomicAdd(dst + 0, r01.x);
    atomicAdd(dst + 1, r01.y);
    atomicAdd(dst + 2, r23.x);
    atomicAdd(dst + 3, r23.y);
}

// ---------------- final MLP ----------------
__global__ void fc_kernel(const float* __restrict__ pool, const int* __restrict__ gstart,
                          const float* __restrict__ W1, const float* __restrict__ b1,
                          const float* __restrict__ W2, const float* __restrict__ b2,
                          float* __restrict__ out) {
    int g = blockIdx.x, t = threadIdx.x;
    __shared__ float xp[432];
    __shared__ float ws[4];
    float cntf = (float)(gstart[g + 1] - gstart[g]);
    float invc = 1.f / fmaxf(cntf, 1.f);
    for (int i = t; i < 432; i += 128) xp[i] = pool[g * 432 + i] * invc;
    __syncthreads();
    float acc = b1[t];
    for (int i = 0; i < 432; i++) acc += xp[i] * W1[i * 128 + t];
    acc = fmaxf(acc, 0.f);
    float v = acc * W2[t];
#pragma unroll
    for (int o = 16; o; o >>= 1) v += __shfl_xor_sync(0xffffffffu, v, o);
    if ((t & 31) == 0) ws[t >> 5] = v;
    __syncthreads();
    if (t == 0) out[g] = ws[0] + ws[1] + ws[2] + ws[3] + b2[0];
}

// ---------------- launch ----------------
extern "C" void kernel_launch(void* const* d_in, const int* in_sizes, int n_in,
                              void* d_out, int out_size) {
    const float* x    = (const float*)d_in[0];
    const int*   ei   = (const int*)d_in[1];
    const int*   batch= (const int*)d_in[2];
    const float* W1   = (const float*)d_in[3];
    const float* b1   = (const float*)d_in[4];
    const float* W2   = (const float*)d_in[5];
    const float* b2   = (const float*)d_in[6];
    const float* W3   = (const float*)d_in[7];
    const float* as3  = (const float*)d_in[8];
    const float* ad3  = (const float*)d_in[9];
    const float* b3   = (const float*)d_in[10];
    const float* W4   = (const float*)d_in[11];
    const float* as4  = (const float*)d_in[12];
    const float* ad4  = (const float*)d_in[13];
    const float* b4   = (const float*)d_in[14];
    const float* Wfc1 = (const float*)d_in[15];
    const float* bfc1 = (const float*)d_in[16];
    const float* Wfc2 = (const float*)d_in[17];
    const float* bfc2 = (const float*)d_in[18];
    float* out = (float*)d_out;

    constexpr int SMEM3 = 64 * 80 + 128 * 80 + 2 * 4 * 32 * 4;     // 16384
    constexpr int SMEM4 = 64 * 272 + 256 * 272 + 2 * 8 * 32 * 4;   // 89088

    static float *p_x1 = nullptr, *p_x2, *p_h, *p_h2, *p_asrc, *p_adst, *p_dinv, *p_pool;
    static __half *p_hb, *p_x2b, *p_x3b, *p_x4b, *p_w3t, *p_w4t;
    static int *p_counts, *p_rank, *p_bsum, *p_rowptr, *p_csr, *p_gstart;
    static cudaStream_t s1, s2;
    static cudaEvent_t evRoot, evG1, evW, evX1, evX2, evX3, evX4, evFC;
    if (!p_x1) {
        cudaGetSymbolAddress((void**)&p_x1, g_x1);
        cudaGetSymbolAddress((void**)&p_x2, g_x2);
        cudaGetSymbolAddress((void**)&p_h, g_h);
        cudaGetSymbolAddress((void**)&p_h2, g_h2);
        cudaGetSymbolAddress((void**)&p_hb, g_hb);
        cudaGetSymbolAddress((void**)&p_x2b, g_x2b);
        cudaGetSymbolAddress((void**)&p_x3b, g_x3b);
        cudaGetSymbolAddress((void**)&p_x4b, g_x4b);
        cudaGetSymbolAddress((void**)&p_w3t, g_w3t);
        cudaGetSymbolAddress((void**)&p_w4t, g_w4t);
        cudaGetSymbolAddress((void**)&p_asrc, g_asrc);
        cudaGetSymbolAddress((void**)&p_adst, g_adst);
        cudaGetSymbolAddress((void**)&p_dinv, g_dinv);
        cudaGetSymbolAddress((void**)&p_pool, g_pool);
        cudaGetSymbolAddress((void**)&p_counts, g_counts);
        cudaGetSymbolAddress((void**)&p_rank, g_rank);
        cudaGetSymbolAddress((void**)&p_bsum, g_bsum);
        cudaGetSymbolAddress((void**)&p_rowptr, g_rowptr);
        cudaGetSymbolAddress((void**)&p_csr, g_csr_src);
        cudaGetSymbolAddress((void**)&p_gstart, g_gstart);
        cudaStreamCreateWithFlags(&s1, cudaStreamNonBlocking);
        cudaStreamCreateWithFlags(&s2, cudaStreamNonBlocking);
        cudaEventCreateWithFlags(&evRoot, cudaEventDisableTiming);
        cudaEventCreateWithFlags(&evG1, cudaEventDisableTiming);
        cudaEventCreateWithFlags(&evW, cudaEventDisableTiming);
        cudaEventCreateWithFlags(&evX1, cudaEventDisableTiming);
        cudaEventCreateWithFlags(&evX2, cudaEventDisableTiming);
        cudaEventCreateWithFlags(&evX3, cudaEventDisableTiming);
        cudaEventCreateWithFlags(&evX4, cudaEventDisableTiming);
        cudaEventCreateWithFlags(&evFC, cudaEventDisableTiming);
        cudaFuncSetAttribute((const void*)gemm_mma_kernel<32, 128>,
                             cudaFuncAttributeMaxDynamicSharedMemorySize, SMEM3);
        cudaFuncSetAttribute((const void*)gemm_mma_kernel<128, 256>,
                             cudaFuncAttributeMaxDynamicSharedMemorySize, SMEM4);
    }

    // fork
    cudaEventRecord(evRoot, 0);
    cudaStreamWaitEvent(s1, evRoot, 0);
    cudaStreamWaitEvent(s2, evRoot, 0);

    // s0: CSR chain (real edges only; self-loops handled in scan_apply; counts
    // self-reset each call so no memset is needed)
    count_edges_kernel<<<(EE + 255) / 256, 256>>>(ei, p_counts, p_rank);
    scan_reduce_kernel<<<RB, 1024>>>(p_counts, p_bsum);
    scan_apply_kernel<<<RB, 1024>>>(p_counts, p_bsum, p_rowptr, p_dinv, p_csr);
    fill_csr_kernel<<<(EE + 255) / 256, 256>>>(ei, p_rowptr, p_rank, p_csr);

    // s1: gstart + pool init + W transposes (independent)
    gstart_kernel<<<(NN + 255) / 256, 256, 0, s1>>>(batch, p_gstart);
    cudaMemsetAsync(p_pool, 0, GG * 432 * sizeof(float), s1);
    wt_kernel<32, 128><<<(128 * 32 + 255) / 256, 256, 0, s1>>>(W3, p_w3t);
    wt_kernel<128, 256><<<(256 * 128 + 255) / 256, 256, 0, s1>>>(W4, p_w4t);
    cudaEventRecord(evW, s1);

    // s2: GEMM1 (independent of CSR)
    {
        dim3 b(4, 16), g((NN + 63) / 64, 1);
        gemm_small_kernel<128, 16><<<g, b, 0, s2>>>(x, W1, p_h);
        cudaEventRecord(evG1, s2);
    }

    // GCN layer 1 aggregate + fused x1@W2 GEMM
    cudaStreamWaitEvent(0, evG1, 0);
    gcn1_fused_kernel<<<(NN * 4 + 255) / 256, 256>>>(p_h, p_dinv, p_rowptr, p_csr, b1, W2,
                                                     p_x1, p_h2);
    cudaEventRecord(evX1, 0);
    cudaStreamWaitEvent(s1, evX1, 0);
    pool_part_kernel<4><<<dim3(GG, 1), 128, 0, s1>>>(p_x1, 0, 1, p_gstart, p_pool);

    // GCN layer 2 aggregate
    gcn_agg_kernel<32><<<(NN * 8 + 255) / 256, 256>>>(p_h2, p_dinv, p_rowptr, p_csr, b2, p_x2, p_x2b);
    cudaEventRecord(evX2, 0);
    cudaStreamWaitEvent(s1, evX2, 0);
    pool_part_kernel<8><<<dim3(GG, 1), 128, 0, s1>>>(p_x2, 16, 1, p_gstart, p_pool);

    // GAT layer 3 (32 -> 4x32): HMMA + fused-softmax aggregation (fp16 out)
    cudaStreamWaitEvent(0, evW, 0);
    gemm_mma_kernel<32, 128><<<(NN + 63) / 64, 256, SMEM3>>>(p_x2b, p_w3t, as3, ad3,
                                                             p_hb, p_asrc, p_adst);
    gat_agg_kernel<4><<<NN / 4, 128>>>(p_hb, p_asrc, p_adst, p_rowptr, p_csr, b3, p_x3b);
    cudaEventRecord(evX3, 0);
    cudaStreamWaitEvent(s1, evX3, 0);
    pool_parth_kernel<32><<<dim3(GG, 2), 128, 0, s1>>>(p_x3b, 48, 2, p_gstart, p_pool);

    // GAT layer 4 (128 -> 8x32): HMMA + fused-softmax aggregation (fp16 out)
    gemm_mma_kernel<128, 256><<<(NN + 63) / 64, 256, SMEM4>>>(p_x3b, p_w4t, as4, ad4,
                                                              p_hb, p_asrc, p_adst);
    gat_agg_kernel<8><<<NN / 2, 128>>>(p_hb, p_asrc, p_adst, p_rowptr, p_csr, b4, p_x4b);
    cudaEventRecord(evX4, 0);
    cudaStreamWaitEvent(s1, evX4, 0);
    pool_parth_kernel<64><<<dim3(GG, 4), 128, 0, s1>>>(p_x4b, 176, 4, p_gstart, p_pool);

    // FC on s1
    fc_kernel<<<GG, 128, 0, s1>>>(p_pool, p_gstart, Wfc1, bfc1, Wfc2, bfc2, out);
    cudaEventRecord(evFC, s1);
    cudaStreamWaitEvent(0, evFC, 0);
}

// round 16
// speedup vs baseline: 1.0398x; 1.0002x over previous
#include <cuda_runtime.h>
#include <cuda_fp16.h>
#include <cstdint>

#define NN 50000
#define EE 800000
#define ETOT (EE + NN)
#define GG 128
#define NEG_SLOPE 0.2f
#define RB 49   // ceil(NN/1024)

typedef unsigned long long ull;

union F4U { float4 f; ull u[2]; };
union F2U { float2 f; ull u; };

__device__ __forceinline__ ull fma2(ull a, ull b, ull c) {
    ull d; asm("fma.rn.f32x2 %0,%1,%2,%3;" : "=l"(d) : "l"(a), "l"(b), "l"(c)); return d;
}
__device__ __forceinline__ ull add2(ull a, ull b) {
    ull d; asm("add.rn.f32x2 %0,%1,%2;" : "=l"(d) : "l"(a), "l"(b)); return d;
}
__device__ __forceinline__ ull pack2(float x) {
    F2U t; t.f = make_float2(x, x); return t.u;
}
__device__ __forceinline__ float2 unpack2(ull v) { F2U t; t.u = v; return t.f; }

__device__ __forceinline__ uint32_t smem_u32(const void* p) {
    uint32_t a;
    asm("{ .reg .u64 t; cvta.to.shared.u64 t, %1; cvt.u32.u64 %0, t; }" : "=r"(a) : "l"(p));
    return a;
}
__device__ __forceinline__ void ldsm4(uint32_t& r0, uint32_t& r1, uint32_t& r2, uint32_t& r3,
                                      uint32_t addr) {
    asm volatile("ldmatrix.sync.aligned.m8n8.x4.shared.b16 {%0,%1,%2,%3}, [%4];"
                 : "=r"(r0), "=r"(r1), "=r"(r2), "=r"(r3) : "r"(addr));
}
__device__ __forceinline__ void mma16816(float* c, uint32_t a0, uint32_t a1, uint32_t a2,
                                         uint32_t a3, uint32_t b0, uint32_t b1) {
    asm volatile(
        "mma.sync.aligned.m16n8k16.row.col.f32.f16.f16.f32 "
        "{%0,%1,%2,%3},{%4,%5,%6,%7},{%8,%9},{%0,%1,%2,%3};"
        : "+f"(c[0]), "+f"(c[1]), "+f"(c[2]), "+f"(c[3])
        : "r"(a0), "r"(a1), "r"(a2), "r"(a3), "r"(b0), "r"(b1));
}

// ---------------- scratch ----------------
__device__ float g_x1[NN * 16];
__device__ float g_x2[NN * 32];
__device__ __half g_h [NN * 16];       // x@W1 pre-agg (fp16)
__device__ __half g_h2[NN * 32];       // x1@W2 pre-agg (fp16)
__device__ __half g_hb[NN * 256];
__device__ __half g_x2b[NN * 32];
__device__ __half g_x3b[NN * 128];
__device__ __half g_x4b[NN * 256];
__device__ __half g_w3t[128 * 32];
__device__ __half g_w4t[256 * 128];
__device__ float g_asrc[NN * 8];
__device__ float g_adst[NN * 8];
__device__ float g_dinv[NN];
__device__ int   g_counts[NN];          // statically zero; every call restores zeros
__device__ int   g_rank[EE];
__device__ int   g_bsum[RB];
__device__ int   g_rowptr[NN + 1];
__device__ int   g_csr_src[ETOT];
__device__ int   g_gstart[GG + 1];
__device__ float g_pool[GG * 432];

// ---------------- CSR build ----------------
__global__ void count_edges_kernel(const int* __restrict__ ei, int* __restrict__ counts,
                                   int* __restrict__ rank) {
    int e = blockIdx.x * blockDim.x + threadIdx.x;
    if (e >= EE) return;
    int dst = ei[EE + e];
    rank[e] = atomicAdd(&counts[dst], 1);
}

__global__ void scan_reduce_kernel(const int* __restrict__ counts, int* __restrict__ bsum) {
    __shared__ int ws[32];
    int i = blockIdx.x * 1024 + threadIdx.x;
    int v = (i < NN) ? counts[i] : 0;
    int lane = threadIdx.x & 31, w = threadIdx.x >> 5;
#pragma unroll
    for (int o = 16; o; o >>= 1) v += __shfl_xor_sync(0xffffffffu, v, o);
    if (lane == 0) ws[w] = v;
    __syncthreads();
    if (w == 0) {
        int s = ws[lane];
#pragma unroll
        for (int o = 16; o; o >>= 1) s += __shfl_xor_sync(0xffffffffu, s, o);
        if (lane == 0) bsum[blockIdx.x] = s;
    }
}

__global__ void scan_apply_kernel(int* __restrict__ counts, const int* __restrict__ bsum,
                                  int* __restrict__ rowptr, float* __restrict__ dinv,
                                  int* __restrict__ csr) {
    __shared__ int ws[32];
    __shared__ int boff_sh;
    int i = blockIdx.x * 1024 + threadIdx.x;
    int cnt = (i < NN) ? counts[i] : 0;
    int lane = threadIdx.x & 31, w = threadIdx.x >> 5;
    int v = cnt;
#pragma unroll
    for (int o = 1; o < 32; o <<= 1) {
        int u = __shfl_up_sync(0xffffffffu, v, o);
        if (lane >= o) v += u;
    }
    if (lane == 31) ws[w] = v;
    __syncthreads();
    if (w == 0) {
        int s = ws[lane];
#pragma unroll
        for (int o = 1; o < 32; o <<= 1) {
            int u = __shfl_up_sync(0xffffffffu, s, o);
            if (lane >= o) s += u;
        }
        ws[lane] = s;
    }
    if (w == 1) {
        int lim = (int)blockIdx.x < RB ? (int)blockIdx.x : RB;
        int v2 = (lane < lim) ? bsum[lane] : 0;
        if (lane + 32 < lim) v2 += bsum[lane + 32];
#pragma unroll
        for (int o = 16; o; o >>= 1) v2 += __shfl_xor_sync(0xffffffffu, v2, o);
        if (lane == 0) boff_sh = v2;
    }
    __syncthreads();
    int incl = v + (w ? ws[w - 1] : 0) + boff_sh;
    if (i < NN) {
        rowptr[i + 1] = incl + i + 1;
        csr[incl + i] = i;
        dinv[i] = rsqrtf((float)(cnt + 1));
        counts[i] = 0;
    }
    if (i == 0) rowptr[0] = 0;
}

__global__ void fill_csr_kernel(const int* __restrict__ ei, const int* __restrict__ rowptr,
                                const int* __restrict__ rank, int* __restrict__ csr) {
    int e = blockIdx.x * blockDim.x + threadIdx.x;
    if (e >= EE) return;
    int src = ei[e];
    int dst = ei[EE + e];
    csr[rowptr[dst] + rank[e]] = src;
}

__global__ void gstart_kernel(const int* __restrict__ batch, int* __restrict__ gstart) {
    int n = blockIdx.x * blockDim.x + threadIdx.x;
    if (n >= NN) return;
    int b = batch[n];
    if (n == 0) { for (int g = 0; g <= b; g++) gstart[g] = 0; }
    else {
        int pb = batch[n - 1];
        for (int g = pb + 1; g <= b; g++) gstart[g] = n;
    }
    if (n == NN - 1) { for (int g = b + 1; g <= GG; g++) gstart[g] = NN; }
}

// ---- W transpose to fp16 [NOUT][KEL] ----
template<int KEL, int NOUT>
__global__ void wt_kernel(const float* __restrict__ W, __half* __restrict__ Wt) {
    int idx = blockIdx.x * 256 + threadIdx.x;
    if (idx >= KEL * NOUT) return;
    int n = idx / KEL, k = idx % KEL;
    Wt[idx] = __float2half(W[k * NOUT + n]);
}

// ---------------- small GEMM (fp32 compute, fp16 output) ----------------
template<int K, int M>
__global__ void gemm_small_kernel(const float* __restrict__ X, const float* __restrict__ W,
                                  __half* __restrict__ Y) {
    constexpr int CT = M;
    constexpr int KC = (K < 64) ? K : 64;
    constexpr int TX = CT / 4;
    constexpr int NT = TX * 16;
    constexpr int RP = 68;
    __shared__ float Xs[KC * RP];
    __shared__ float Ws[KC * CT];
    int row0 = blockIdx.x * 64;
    int tid = threadIdx.y * TX + threadIdx.x;
    float acc[4][4] = {};
    for (int k0 = 0; k0 < K; k0 += KC) {
        for (int idx = tid; idx < 64 * KC; idx += NT) {
            int r = idx / KC, k = idx % KC;
            int gr = row0 + r;
            Xs[k * RP + r] = (gr < NN) ? X[gr * K + k0 + k] : 0.f;
        }
        for (int idx = tid; idx < KC * CT; idx += NT) {
            int k = idx / CT, c = idx % CT;
            Ws[k * CT + c] = W[(k0 + k) * M + c];
        }
        __syncthreads();
#pragma unroll 8
        for (int k = 0; k < KC; k++) {
            float4 xv = *(const float4*)&Xs[k * RP + 4 * threadIdx.y];
            float4 wv = *(const float4*)&Ws[k * CT + 4 * threadIdx.x];
            float xa[4] = {xv.x, xv.y, xv.z, xv.w};
            float wa[4] = {wv.x, wv.y, wv.z, wv.w};
#pragma unroll
            for (int i = 0; i < 4; i++)
#pragma unroll
                for (int j = 0; j < 4; j++)
                    acc[i][j] += xa[i] * wa[j];
        }
        __syncthreads();
    }
#pragma unroll
    for (int i = 0; i < 4; i++) {
        int r = row0 + 4 * threadIdx.y + i;
        if (r < NN) {
            __half2 p0 = __floats2half2_rn(acc[i][0], acc[i][1]);
            __half2 p1 = __floats2half2_rn(acc[i][2], acc[i][3]);
            uint2 u; u.x = *(uint32_t*)&p0; u.y = *(uint32_t*)&p1;
            *(uint2*)&Y[r * M + 4 * threadIdx.x] = u;
        }
    }
}

// ---------------- HMMA GEMM: h = X@W (fp16 in/out), fused attention coefficients ----------------
template<int KEL, int NOUT>
__global__ __launch_bounds__(256) void gemm_mma_kernel(
        const __half* __restrict__ Xb, const __half* __restrict__ Wt,
        const float* __restrict__ att_s, const float* __restrict__ att_d,
        __half* __restrict__ Yb, float* __restrict__ asrc, float* __restrict__ adst) {
    constexpr int H = NOUT / 32;
    constexpr int KP = KEL + 8;
    constexpr int KPB = KP * 2;
    constexpr int A_OFF = 0;
    constexpr int B_OFF = 64 * KPB;
    constexpr int ATT_OFF = B_OFF + NOUT * KPB;
    constexpr int AU = KEL / 8;
    constexpr int NTILES = NOUT / 16;

    extern __shared__ char smem[];
    uint32_t sb = smem_u32(smem);
    int tid = threadIdx.x, w = tid >> 5, lane = tid & 31;
    int row0 = blockIdx.x * 64;

    for (int idx = tid; idx < 64 * AU; idx += 256) {
        int r = idx / AU, u = idx % AU;
        int gr = row0 + r;
        uint4 v = make_uint4(0, 0, 0, 0);
        if (gr < NN) v = *(const uint4*)&Xb[(size_t)gr * KEL + u * 8];
        *(uint4*)(smem + A_OFF + r * KPB + u * 16) = v;
    }
    for (int idx = tid; idx < NOUT * AU; idx += 256) {
        int r = idx / AU, u = idx % AU;
        *(uint4*)(smem + B_OFF + r * KPB + u * 16) = *(const uint4*)&Wt[r * KEL + u * 8];
    }
    float* att_sh = (float*)(smem + ATT_OFF);
    for (int idx = tid; idx < 2 * H * 32; idx += 256)
        att_sh[idx] = (idx < H * 32) ? att_s[idx] : att_d[idx - H * 32];
    __syncthreads();

    int wr = w >> 1, wc = w & 1;
    float acc[NTILES][4];
#pragma unroll
    for (int t = 0; t < NTILES; t++)
#pragma unroll
        for (int q = 0; q < 4; q++) acc[t][q] = 0.f;

    uint32_t aaddr = sb + A_OFF + (wr * 16 + (lane & 15)) * KPB + ((lane >> 4) << 4);
    uint32_t baddr = sb + B_OFF +
                     (wc * (NOUT / 2) + (lane & 7) + ((lane >> 4) << 3)) * KPB +
                     (((lane >> 3) & 1) << 4);
#pragma unroll
    for (int ks = 0; ks < KEL / 16; ks++) {
        uint32_t a0, a1, a2, a3;
        ldsm4(a0, a1, a2, a3, aaddr + ks * 32);
#pragma unroll
        for (int p = 0; p < NTILES / 2; p++) {
            uint32_t b0, b1, b2, b3;
            ldsm4(b0, b1, b2, b3, baddr + p * 16 * KPB + ks * 32);
            mma16816(acc[2 * p],     a0, a1, a2, a3, b0, b1);
            mma16816(acc[2 * p + 1], a0, a1, a2, a3, b2, b3);
        }
    }

    int g = lane >> 2;
    int r0g = row0 + wr * 16 + g;
    int r1g = r0g + 8;
    constexpr int HLOC = H / 2;
#pragma unroll
    for (int hh = 0; hh < HLOC; hh++) {
        int ghead = wc * HLOC + hh;
        float s0 = 0.f, d0 = 0.f, s1 = 0.f, d1 = 0.f;
#pragma unroll
        for (int t4 = 0; t4 < 4; t4++) {
            int t = hh * 4 + t4;
            int cih = t4 * 8 + (lane & 3) * 2;
            float aS0 = att_sh[ghead * 32 + cih];
            float aS1 = att_sh[ghead * 32 + cih + 1];
            float aD0 = att_sh[H * 32 + ghead * 32 + cih];
            float aD1 = att_sh[H * 32 + ghead * 32 + cih + 1];
            s0 += acc[t][0] * aS0 + acc[t][1] * aS1;
            d0 += acc[t][0] * aD0 + acc[t][1] * aD1;
            s1 += acc[t][2] * aS0 + acc[t][3] * aS1;
            d1 += acc[t][2] * aD0 + acc[t][3] * aD1;
        }
#pragma unroll
        for (int o = 1; o <= 2; o <<= 1) {
            s0 += __shfl_xor_sync(0xffffffffu, s0, o);
            d0 += __shfl_xor_sync(0xffffffffu, d0, o);
            s1 += __shfl_xor_sync(0xffffffffu, s1, o);
            d1 += __shfl_xor_sync(0xffffffffu, d1, o);
        }
        if ((lane & 3) == 0) {
            if (r0g < NN) { asrc[r0g * H + ghead] = s0; adst[r0g * H + ghead] = d0; }
            if (r1g < NN) { asrc[r1g * H + ghead] = s1; adst[r1g * H + ghead] = d1; }
        }
    }
#pragma unroll
    for (int t = 0; t < NTILES; t++) {
        int col = wc * (NOUT / 2) + t * 8 + (lane & 3) * 2;
        if (r0g < NN) {
            __half2 h2 = __floats2half2_rn(acc[t][0], acc[t][1]);
            *(uint32_t*)&Yb[(size_t)r0g * NOUT + col] = *(uint32_t*)&h2;
        }
        if (r1g < NN) {
            __half2 h2 = __floats2half2_rn(acc[t][2], acc[t][3]);
            *(uint32_t*)&Yb[(size_t)r1g * NOUT + col] = *(uint32_t*)&h2;
        }
    }
}

// ---------------- GCN layer-1 aggregate (fp16 gather) + fused x1@W2 GEMM (fp16 out) ----------
__global__ __launch_bounds__(256) void gcn1_fused_kernel(
        const __half* __restrict__ h, const float* __restrict__ dinv,
        const int* __restrict__ rowptr, const int* __restrict__ csr,
        const float* __restrict__ bias, const float* __restrict__ W2,
        float* __restrict__ x1out, __half* __restrict__ h2out) {
    __shared__ float W2s[512];
    int tid = threadIdx.x;
    for (int idx = tid; idx < 512; idx += 256) W2s[idx] = W2[idx];
    __syncthreads();

    int gtid = blockIdx.x * 256 + tid;
    int n = gtid >> 2;
    int tg = tid & 3;
    int lane = tid & 31;
    bool valid = n < NN;
    int ch = 4 * tg;
    int r0 = 0, r1 = 0;
    if (valid) { r0 = rowptr[n]; r1 = rowptr[n + 1]; }
    const __half* hb = h + ch;
    ull a0 = 0ull, a1 = 0ull;
    for (int j = r0; j < r1; j++) {
        int s = csr[j];
        ull dv2 = pack2(dinv[s]);
        uint2 v = *(const uint2*)(hb + s * 16);
        F2U f0, f1;
        f0.f = __half22float2(*(__half2*)&v.x);
        f1.f = __half22float2(*(__half2*)&v.y);
        a0 = fma2(f0.u, dv2, a0);
        a1 = fma2(f1.u, dv2, a1);
    }
    float dn = valid ? dinv[n] : 0.f;
    float2 r01 = unpack2(a0), r23 = unpack2(a1);
    float4 b = *(const float4*)&bias[ch];
    float4 o;
    o.x = fmaxf(r01.x * dn + b.x, 0.f);
    o.y = fmaxf(r01.y * dn + b.y, 0.f);
    o.z = fmaxf(r23.x * dn + b.z, 0.f);
    o.w = fmaxf(r23.y * dn + b.w, 0.f);
    if (valid) *(float4*)&x1out[n * 16 + ch] = o;

    float xv[16];
    int baseq = lane & ~3;
#pragma unroll
    for (int q = 0; q < 4; q++) {
        xv[4 * q + 0] = __shfl_sync(0xffffffffu, o.x, baseq + q);
        xv[4 * q + 1] = __shfl_sync(0xffffffffu, o.y, baseq + q);
        xv[4 * q + 2] = __shfl_sync(0xffffffffu, o.z, baseq + q);
        xv[4 * q + 3] = __shfl_sync(0xffffffffu, o.w, baseq + q);
    }
    float acc8[8] = {};
#pragma unroll
    for (int k = 0; k < 16; k++) {
        const float* wr = &W2s[k * 32 + 8 * tg];
        float4 wa = *(const float4*)wr;
        float4 wb = *(const float4*)(wr + 4);
        acc8[0] += xv[k] * wa.x; acc8[1] += xv[k] * wa.y;
        acc8[2] += xv[k] * wa.z; acc8[3] += xv[k] * wa.w;
        acc8[4] += xv[k] * wb.x; acc8[5] += xv[k] * wb.y;
        acc8[6] += xv[k] * wb.z; acc8[7] += xv[k] * wb.w;
    }
    if (valid) {
        __half2 p0 = __floats2half2_rn(acc8[0], acc8[1]);
        __half2 p1 = __floats2half2_rn(acc8[2], acc8[3]);
        __half2 p2 = __floats2half2_rn(acc8[4], acc8[5]);
        __half2 p3 = __floats2half2_rn(acc8[6], acc8[7]);
        uint4 u;
        u.x = *(uint32_t*)&p0; u.y = *(uint32_t*)&p1;
        u.z = *(uint32_t*)&p2; u.w = *(uint32_t*)&p3;
        *(uint4*)&h2out[n * 32 + 8 * tg] = u;
    }
}

// ---------------- GCN layer-2 aggregate: fp16 gather, fp32+fp16 out ----------------
__global__ void gcn_agg2_kernel(const __half* __restrict__ h, const float* __restrict__ dinv,
                                const int* __restrict__ rowptr, const int* __restrict__ csr,
                                const float* __restrict__ bias, float* __restrict__ out,
                                __half* __restrict__ outb) {
    constexpr int C = 32;
    constexpr int TPN = C / 4;
    int gtid = blockIdx.x * blockDim.x + threadIdx.x;
    int n = gtid / TPN;
    int ch = 4 * (gtid % TPN);
    if (n >= NN) return;
    int r0 = rowptr[n], r1 = rowptr[n + 1];
    const __half* hb = h + ch;
    ull a0 = 0ull, a1 = 0ull;
    for (int j = r0; j < r1; j++) {
        int s = csr[j];
        ull dv2 = pack2(dinv[s]);
        uint2 v = *(const uint2*)(hb + s * C);
        F2U f0, f1;
        f0.f = __half22float2(*(__half2*)&v.x);
        f1.f = __half22float2(*(__half2*)&v.y);
        a0 = fma2(f0.u, dv2, a0);
        a1 = fma2(f1.u, dv2, a1);
    }
    float dn = dinv[n];
    float2 r01 = unpack2(a0), r23 = unpack2(a1);
    float4 b = *(const float4*)&bias[ch];
    float4 o;
    o.x = fmaxf(r01.x * dn + b.x, 0.f);
    o.y = fmaxf(r01.y * dn + b.y, 0.f);
    o.z = fmaxf(r23.x * dn + b.z, 0.f);
    o.w = fmaxf(r23.y * dn + b.w, 0.f);
    *(float4*)&out[n * C + ch] = o;
    __half2 p0 = __floats2half2_rn(o.x, o.y);
    __half2 p1 = __floats2half2_rn(o.z, o.w);
    uint2 u; u.x = *(uint32_t*)&p0; u.y = *(uint32_t*)&p1;
    *(uint2*)&outb[n * C + ch] = u;
}

// ---------------- GAT aggregation: fused softmax, fp16 in/out ----------------
template<int H>
__global__ __launch_bounds__(128) void gat_agg_kernel(
        const __half* __restrict__ h, const float* __restrict__ asrc,
        const float* __restrict__ adst, const int* __restrict__ rowptr,
        const int* __restrict__ csr, const float* __restrict__ bias,
        __half* __restrict__ outb) {
    constexpr int HC = H * 32;
    constexpr int TPN = HC / 4;
    constexpr int NPB = 128 / TPN;
    constexpr int CH = 32;
    __shared__ float2 al_sh[NPB][CH * H];
    __shared__ int off_sh[NPB][CH];
    __shared__ float ad_sh[NPB][H];
    __shared__ int r0_sh[NPB];
    __shared__ int cnt_sh[NPB];
    __shared__ int mx_sh;

    int tid = threadIdx.x;
    int g = tid / TPN, tg = tid % TPN;
    int n = blockIdx.x * NPB + g;
    if (tid == 0) mx_sh = 0;
    if (tg < H) ad_sh[g][tg] = adst[n * H + tg];
    if (tg == 0) {
        int r0 = rowptr[n], r1 = rowptr[n + 1];
        r0_sh[g] = r0;
        cnt_sh[g] = r1 - r0;
    }
    __syncthreads();
    if (tg == 0) atomicMax(&mx_sh, cnt_sh[g]);
    __syncthreads();
    int cnt = cnt_sh[g], r0 = r0_sh[g];
    int nch = (mx_sh + CH - 1) / CH;
    int ch0 = 4 * tg;
    int hd = tg >> 3;
    const __half* hb = h + ch0;
    ull a0 = 0ull, a1 = 0ull;
    float den = 0.f;

    for (int c = 0; c < nch; c++) {
        int base = c * CH;
        int cc = min(CH, cnt - base);
#pragma unroll
        for (int it = 0; it < CH * H / TPN; it++) {
            int task = tg + it * TPN;
            int e = task / H;
            int hh = task - e * H;
            if (e < cc) {
                int j = r0 + base + e;
                int src = csr[j];
                float el = asrc[src * H + hh] + ad_sh[g][hh];
                el = fmaxf(el, NEG_SLOPE * el);
                float ev = __expf(el);
                al_sh[g][task] = make_float2(ev, ev);
                if (hh == 0) off_sh[g][e] = src * HC;
            }
        }
        __syncthreads();
        int e = 0;
        for (; e + 4 <= cc; e += 4) {
            int o0 = off_sh[g][e], o1 = off_sh[g][e + 1], o2 = off_sh[g][e + 2], o3 = off_sh[g][e + 3];
            F2U A0, A1, A2, A3;
            A0.f = al_sh[g][(e + 0) * H + hd];
            A1.f = al_sh[g][(e + 1) * H + hd];
            A2.f = al_sh[g][(e + 2) * H + hd];
            A3.f = al_sh[g][(e + 3) * H + hd];
            den += A0.f.x + A1.f.x + A2.f.x + A3.f.x;
            uint2 v0 = *(const uint2*)(hb + o0);
            uint2 v1 = *(const uint2*)(hb + o1);
            uint2 v2 = *(const uint2*)(hb + o2);
            uint2 v3 = *(const uint2*)(hb + o3);
            F2U f;
            f.f = __half22float2(*(__half2*)&v0.x); a0 = fma2(f.u, A0.u, a0);
            f.f = __half22float2(*(__half2*)&v0.y); a1 = fma2(f.u, A0.u, a1);
            f.f = __half22float2(*(__half2*)&v1.x); a0 = fma2(f.u, A1.u, a0);
            f.f = __half22float2(*(__half2*)&v1.y); a1 = fma2(f.u, A1.u, a1);
            f.f = __half22float2(*(__half2*)&v2.x); a0 = fma2(f.u, A2.u, a0);
            f.f = __half22float2(*(__half2*)&v2.y); a1 = fma2(f.u, A2.u, a1);
            f.f = __half22float2(*(__half2*)&v3.x); a0 = fma2(f.u, A3.u, a0);
            f.f = __half22float2(*(__half2*)&v3.y); a1 = fma2(f.u, A3.u, a1);
        }
        for (; e < cc; e++) {
            int o = off_sh[g][e];
            F2U A; A.f = al_sh[g][e * H + hd];
            den += A.f.x;
            uint2 v = *(const uint2*)(hb + o);
            F2U f;
            f.f = __half22float2(*(__half2*)&v.x); a0 = fma2(f.u, A.u, a0);
            f.f = __half22float2(*(__half2*)&v.y); a1 = fma2(f.u, A.u, a1);
        }
        __syncthreads();
    }
    float invd = 1.f / den;
    float2 r01 = unpack2(a0), r23 = unpack2(a1);
    float4 b = *(const float4*)&bias[ch0];
    float4 o;
    o.x = fmaxf(r01.x * invd + b.x, 0.f);
    o.y = fmaxf(r01.y * invd + b.y, 0.f);
    o.z = fmaxf(r23.x * invd + b.z, 0.f);
    o.w = fmaxf(r23.y * invd + b.w, 0.f);
    __half2 p0 = __floats2half2_rn(o.x, o.y);
    __half2 p1 = __floats2half2_rn(o.z, o.w);
    uint2 u; u.x = *(uint32_t*)&p0; u.y = *(uint32_t*)&p1;
    *(uint2*)&outb[n * HC + ch0] = u;
}

// ---------------- pooling partials: fp32 source ----------------
template<int NF4>
__global__ void pool_part_kernel(const float* __restrict__ src, int obase, int qy_total,
                                 const int* __restrict__ gstart, float* __restrict__ pool) {
    constexpr int SPB = 128 / NF4;
    int g = blockIdx.x;
    int q = blockIdx.y * SPB + threadIdx.x / NF4;
    int f = threadIdx.x % NF4;
    int slices = qy_total * SPB;
    int s = gstart[g], e = gstart[g + 1];
    int len = e - s;
    int n0 = s + (int)((long long)len * q / slices);
    int n1 = s + (int)((long long)len * (q + 1) / slices);
    ull a0 = 0ull, a1 = 0ull;
    int stride = NF4 * 4;
    for (int n = n0; n < n1; n++) {
        F4U v; v.f = *(const float4*)&src[(size_t)n * stride + 4 * f];
        a0 = add2(a0, v.u[0]);
        a1 = add2(a1, v.u[1]);
    }
    float2 r01 = unpack2(a0), r23 = unpack2(a1);
    float* dst = &pool[g * 432 + obase + 4 * f];
    atomicAdd(dst + 0, r01.x);
    atomicAdd(dst + 1, r01.y);
    atomicAdd(dst + 2, r23.x);
    atomicAdd(dst + 3, r23.y);
}

// ---------------- pooling partials: fp16 source ----------------
template<int NF4>
__global__ void pool_parth_kernel(const __half* __restrict__ src, int obase, int qy_total,
                                  const int* __restrict__ gstart, float* __restrict__ pool) {
    constexpr int SPB = 128 / NF4;
    int g = blockIdx.x;
    int q = blockIdx.y * SPB + threadIdx.x / NF4;
    int f = threadIdx.x % NF4;
    int slices = qy_total * SPB;
    int s = gstart[g], e = gstart[g + 1];
    int len = e - s;
    int n0 = s + (int)((long long)len * q / slices);
    int n1 = s + (int)((long long)len * (q + 1) / slices);
    ull a0 = 0ull, a1 = 0ull;
    int stride = NF4 * 4;
    for (int n = n0; n < n1; n++) {
        uint2 v = *(const uint2*)&src[(size_t)n * stride + 4 * f];
        F2U f0, f1;
        f0.f = __half22float2(*(__half2*)&v.x);
        f1.f = __half22float2(*(__half2*)&v.y);
        a0 = add2(a0, f0.u);
        a1 = add2(a1, f1.u);
    }
    float2 r01 = unpack2(a0), r23 = unpack2(a1);
    float* dst = &pool[g * 432 + obase + 4 * f];
    atomicAdd(dst + 0, r01.x);
    atomicAdd(dst + 1, r01.y);
    atomicAdd(dst + 2, r23.x);
    atomicAdd(dst + 3, r23.y);
}

// ---------------- final MLP ----------------
__global__ void fc_kernel(const float* __restrict__ pool, const int* __restrict__ gstart,
                          const float* __restrict__ W1, const float* __restrict__ b1,
                          const float* __restrict__ W2, const float* __restrict__ b2,
                          float* __restrict__ out) {
    int g = blockIdx.x, t = threadIdx.x;
    __shared__ float xp[432];
    __shared__ float ws[4];
    float cntf = (float)(gstart[g + 1] - gstart[g]);
    float invc = 1.f / fmaxf(cntf, 1.f);
    for (int i = t; i < 432; i += 128) xp[i] = pool[g * 432 + i] * invc;
    __syncthreads();
    float acc = b1[t];
    for (int i = 0; i < 432; i++) acc += xp[i] * W1[i * 128 + t];
    acc = fmaxf(acc, 0.f);
    float v = acc * W2[t];
#pragma unroll
    for (int o = 16; o; o >>= 1) v += __shfl_xor_sync(0xffffffffu, v, o);
    if ((t & 31) == 0) ws[t >> 5] = v;
    __syncthreads();
    if (t == 0) out[g] = ws[0] + ws[1] + ws[2] + ws[3] + b2[0];
}

// ---------------- launch ----------------
extern "C" void kernel_launch(void* const* d_in, const int* in_sizes, int n_in,
                              void* d_out, int out_size) {
    const float* x    = (const float*)d_in[0];
    const int*   ei   = (const int*)d_in[1];
    const int*   batch= (const int*)d_in[2];
    const float* W1   = (const float*)d_in[3];
    const float* b1   = (const float*)d_in[4];
    const float* W2   = (const float*)d_in[5];
    const float* b2   = (const float*)d_in[6];
    const float* W3   = (const float*)d_in[7];
    const float* as3  = (const float*)d_in[8];
    const float* ad3  = (const float*)d_in[9];
    const float* b3   = (const float*)d_in[10];
    const float* W4   = (const float*)d_in[11];
    const float* as4  = (const float*)d_in[12];
    const float* ad4  = (const float*)d_in[13];
    const float* b4   = (const float*)d_in[14];
    const float* Wfc1 = (const float*)d_in[15];
    const float* bfc1 = (const float*)d_in[16];
    const float* Wfc2 = (const float*)d_in[17];
    const float* bfc2 = (const float*)d_in[18];
    float* out = (float*)d_out;

    constexpr int SMEM3 = 64 * 80 + 128 * 80 + 2 * 4 * 32 * 4;     // 16384
    constexpr int SMEM4 = 64 * 272 + 256 * 272 + 2 * 8 * 32 * 4;   // 89088

    static float *p_x1 = nullptr, *p_x2, *p_asrc, *p_adst, *p_dinv, *p_pool;
    static __half *p_h, *p_h2, *p_hb, *p_x2b, *p_x3b, *p_x4b, *p_w3t, *p_w4t;
    static int *p_counts, *p_rank, *p_bsum, *p_rowptr, *p_csr, *p_gstart;
    static cudaStream_t s1, s2;
    static cudaEvent_t evRoot, evG1, evW, evX1, evX2, evX3, evX4, evFC;
    if (!p_x1) {
        cudaGetSymbolAddress((void**)&p_x1, g_x1);
        cudaGetSymbolAddress((void**)&p_x2, g_x2);
        cudaGetSymbolAddress((void**)&p_h, g_h);
        cudaGetSymbolAddress((void**)&p_h2, g_h2);
        cudaGetSymbolAddress((void**)&p_hb, g_hb);
        cudaGetSymbolAddress((void**)&p_x2b, g_x2b);
        cudaGetSymbolAddress((void**)&p_x3b, g_x3b);
        cudaGetSymbolAddress((void**)&p_x4b, g_x4b);
        cudaGetSymbolAddress((void**)&p_w3t, g_w3t);
        cudaGetSymbolAddress((void**)&p_w4t, g_w4t);
        cudaGetSymbolAddress((void**)&p_asrc, g_asrc);
        cudaGetSymbolAddress((void**)&p_adst, g_adst);
        cudaGetSymbolAddress((void**)&p_dinv, g_dinv);
        cudaGetSymbolAddress((void**)&p_pool, g_pool);
        cudaGetSymbolAddress((void**)&p_counts, g_counts);
        cudaGetSymbolAddress((void**)&p_rank, g_rank);
        cudaGetSymbolAddress((void**)&p_bsum, g_bsum);
        cudaGetSymbolAddress((void**)&p_rowptr, g_rowptr);
        cudaGetSymbolAddress((void**)&p_csr, g_csr_src);
        cudaGetSymbolAddress((void**)&p_gstart, g_gstart);
        cudaStreamCreateWithFlags(&s1, cudaStreamNonBlocking);
        cudaStreamCreateWithFlags(&s2, cudaStreamNonBlocking);
        cudaEventCreateWithFlags(&evRoot, cudaEventDisableTiming);
        cudaEventCreateWithFlags(&evG1, cudaEventDisableTiming);
        cudaEventCreateWithFlags(&evW, cudaEventDisableTiming);
        cudaEventCreateWithFlags(&evX1, cudaEventDisableTiming);
        cudaEventCreateWithFlags(&evX2, cudaEventDisableTiming);
        cudaEventCreateWithFlags(&evX3, cudaEventDisableTiming);
        cudaEventCreateWithFlags(&evX4, cudaEventDisableTiming);
        cudaEventCreateWithFlags(&evFC, cudaEventDisableTiming);
        cudaFuncSetAttribute((const void*)gemm_mma_kernel<32, 128>,
                             cudaFuncAttributeMaxDynamicSharedMemorySize, SMEM3);
        cudaFuncSetAttribute((const void*)gemm_mma_kernel<128, 256>,
                             cudaFuncAttributeMaxDynamicSharedMemorySize, SMEM4);
    }

    // fork
    cudaEventRecord(evRoot, 0);
    cudaStreamWaitEvent(s1, evRoot, 0);
    cudaStreamWaitEvent(s2, evRoot, 0);

    // s0: CSR chain
    count_edges_kernel<<<(EE + 255) / 256, 256>>>(ei, p_counts, p_rank);
    scan_reduce_kernel<<<RB, 1024>>>(p_counts, p_bsum);
    scan_apply_kernel<<<RB, 1024>>>(p_counts, p_bsum, p_rowptr, p_dinv, p_csr);
    fill_csr_kernel<<<(EE + 255) / 256, 256>>>(ei, p_rowptr, p_rank, p_csr);

    // s1: gstart + pool init + W transposes
    gstart_kernel<<<(NN + 255) / 256, 256, 0, s1>>>(batch, p_gstart);
    cudaMemsetAsync(p_pool, 0, GG * 432 * sizeof(float), s1);
    wt_kernel<32, 128><<<(128 * 32 + 255) / 256, 256, 0, s1>>>(W3, p_w3t);
    wt_kernel<128, 256><<<(256 * 128 + 255) / 256, 256, 0, s1>>>(W4, p_w4t);
    cudaEventRecord(evW, s1);

    // s2: GEMM1 (fp16 output)
    {
        dim3 b(4, 16), g((NN + 63) / 64, 1);
        gemm_small_kernel<128, 16><<<g, b, 0, s2>>>(x, W1, p_h);
        cudaEventRecord(evG1, s2);
    }

    // GCN layer 1 aggregate (fp16 gather) + fused x1@W2 GEMM (fp16 h2)
    cudaStreamWaitEvent(0, evG1, 0);
    gcn1_fused_kernel<<<(NN * 4 + 255) / 256, 256>>>(p_h, p_dinv, p_rowptr, p_csr, b1, W2,
                                                     p_x1, p_h2);
    cudaEventRecord(evX1, 0);
    cudaStreamWaitEvent(s1, evX1, 0);
    pool_part_kernel<4><<<dim3(GG, 1), 128, 0, s1>>>(p_x1, 0, 1, p_gstart, p_pool);

    // GCN layer 2 aggregate (fp16 gather)
    gcn_agg2_kernel<<<(NN * 8 + 255) / 256, 256>>>(p_h2, p_dinv, p_rowptr, p_csr, b2, p_x2, p_x2b);
    cudaEventRecord(evX2, 0);
    cudaStreamWaitEvent(s1, evX2, 0);
    pool_part_kernel<8><<<dim3(GG, 1), 128, 0, s1>>>(p_x2, 16, 1, p_gstart, p_pool);

    // GAT layer 3 (32 -> 4x32): HMMA + fused-softmax aggregation (fp16 out)
    cudaStreamWaitEvent(0, evW, 0);
    gemm_mma_kernel<32, 128><<<(NN + 63) / 64, 256, SMEM3>>>(p_x2b, p_w3t, as3, ad3,
                                                             p_hb, p_asrc, p_adst);
    gat_agg_kernel<4><<<NN / 4, 128>>>(p_hb, p_asrc, p_adst, p_rowptr, p_csr, b3, p_x3b);
    cudaEventRecord(evX3, 0);
    cudaStreamWaitEvent(s1, evX3, 0);
    pool_parth_kernel<32><<<dim3(GG, 2), 128, 0, s1>>>(p_x3b, 48, 2, p_gstart, p_pool);

    // GAT layer 4 (128 -> 8x32): HMMA + fused-softmax aggregation (fp16 out)
    gemm_mma_kernel<128, 256><<<(NN + 63) / 64, 256, SMEM4>>>(p_x3b, p_w4t, as4, ad4,
                                                              p_hb, p_asrc, p_adst);
    gat_agg_kernel<8><<<NN / 2, 128>>>(p_hb, p_asrc, p_adst, p_rowptr, p_csr, b4, p_x4b);
    cudaEventRecord(evX4, 0);
    cudaStreamWaitEvent(s1, evX4, 0);
    pool_parth_kernel<64><<<dim3(GG, 4), 128, 0, s1>>>(p_x4b, 176, 4, p_gstart, p_pool);

    // FC on s1
    fc_kernel<<<GG, 128, 0, s1>>>(p_pool, p_gstart, Wfc1, bfc1, Wfc2, bfc2, out);
    cudaEventRecord(evFC, s1);
    cudaStreamWaitEvent(0, evFC, 0);
}